// round 6
// baseline (speedup 1.0000x reference)
#include <cuda_runtime.h>

#define NN 20000
#define EE 50000
#define BB 128
#define HH 64
#define FEATD 28
#define NTYPES 100
#define EDIM 5
#define MPI 3
#define S2S 4

#define TE 128                      // edges per GEMM tile
#define MAXTILES (EE / TE + EDIM)   // worst-case tile count across types

// ---------------- scratch (device globals; no allocation allowed) ----------
__device__ float g_hA[NN * HH];
__device__ float g_hB[NN * HH];
__device__ float g_Wmat[EDIM * HH * HH];
__device__ float g_hx[BB * HH];
__device__ float g_cx[BB * HH];
__device__ float g_qstar[BB * 2 * HH];
__device__ float g_e[NN];
__device__ float g_a[NN];
__device__ int   g_seg[BB + 1];
__device__ int   g_tcnt[EDIM];
__device__ int   g_tptr[EDIM];
__device__ int   g_toff[EDIM + 1];
__device__ int   g_tileoff[EDIM + 1];
__device__ int   g_psrc[EE];
__device__ int   g_pdst[EE];
__device__ int   g_done = 0;

// ======== setup: init state + seg bounds + type hist + (last block) scan ===
__global__ void k_setup(const int* __restrict__ batch,
                        const int* __restrict__ etype) {
    __shared__ int sh[EDIM];
    int tid = threadIdx.x;
    int gid = blockIdx.x * blockDim.x + tid;

    if (tid < EDIM) sh[tid] = 0;

    // init LSTM state + q_star (gid spans >= BB*2*HH)
    if (gid < BB * HH) { g_hx[gid] = 0.f; g_cx[gid] = 0.f; }
    if (gid < BB * 2 * HH) g_qstar[gid] = 0.f;

    // segment bounds (block 0)
    if (blockIdx.x == 0 && tid <= BB) {
        if (tid == BB) g_seg[BB] = NN;
        else {
            int lo = 0, hi = NN;
            while (lo < hi) {
                int mid = (lo + hi) >> 1;
                if (batch[mid] < tid) lo = mid + 1; else hi = mid;
            }
            g_seg[tid] = lo;
        }
    }
    __syncthreads();

    // histogram
    if (gid < EE) atomicAdd(&sh[etype[gid]], 1);
    __syncthreads();
    if (tid < EDIM) atomicAdd(&g_tcnt[tid], sh[tid]);
    __syncthreads();

    // last block performs the scan, then resets counters for next replay
    if (tid == 0) {
        __threadfence();
        int old = atomicAdd(&g_done, 1);
        if (old == (int)gridDim.x - 1) {
            int off = 0, toff = 0;
            for (int t = 0; t < EDIM; t++) {
                int n = atomicAdd(&g_tcnt[t], 0);
                g_toff[t] = off;
                g_tileoff[t] = toff;
                g_tptr[t] = off;
                off += n;
                toff += (n + TE - 1) / TE;
                g_tcnt[t] = 0;         // reset for next replay
            }
            g_toff[EDIM] = off;
            g_tileoff[EDIM] = toff;
            g_done = 0;                // reset for next replay
        }
    }
}

// ======== scatter edges into type-grouped psrc/pdst ========================
__global__ void k_scatter(const int* __restrict__ etype,
                          const int* __restrict__ src,
                          const int* __restrict__ dst) {
    int e = blockIdx.x * blockDim.x + threadIdx.x;
    if (e < EE) {
        int pos = atomicAdd(&g_tptr[etype[e]], 1);
        g_psrc[pos] = src[e];
        g_pdst[pos] = dst[e];
    }
}

// ======== fused: 5 edge weight matrices (blocks 0..63) + embedding =========
__global__ void k_embwmat(const float* __restrict__ W_e1,
                          const float* __restrict__ b_e1,
                          const float* __restrict__ W_e2,
                          const float* __restrict__ b_e2,
                          const float* __restrict__ feat,
                          const int* __restrict__ ntype,
                          const float* __restrict__ W_emb,
                          const float* __restrict__ b_emb) {
    int tid = threadIdx.x;
    if (blockIdx.x < 64) {
        // ---- wmat: W_e2 read once, 4-way j-split ----
        __shared__ float hr[EDIM][HH];
        __shared__ float part[4][EDIM][HH];
        if (tid < HH) {
#pragma unroll
            for (int t = 0; t < EDIM; t++)
                hr[t][tid] = fmaxf(W_e1[t * HH + tid] + b_e1[tid], 0.f);
        }
        __syncthreads();
        int jc = tid >> 6;
        int c = tid & 63;
        int idx = blockIdx.x * 64 + c;
        float a0 = 0.f, a1 = 0.f, a2 = 0.f, a3 = 0.f, a4 = 0.f;
#pragma unroll
        for (int jj = 0; jj < 16; jj++) {
            int j = jc * 16 + jj;
            float w = W_e2[j * (HH * HH) + idx];
            a0 += hr[0][j] * w;
            a1 += hr[1][j] * w;
            a2 += hr[2][j] * w;
            a3 += hr[3][j] * w;
            a4 += hr[4][j] * w;
        }
        part[jc][0][c] = a0; part[jc][1][c] = a1; part[jc][2][c] = a2;
        part[jc][3][c] = a3; part[jc][4][c] = a4;
        __syncthreads();
        if (jc == 0) {
            float bb = b_e2[idx];
#pragma unroll
            for (int t = 0; t < EDIM; t++)
                g_Wmat[t * HH * HH + idx] =
                    bb + part[0][t][c] + part[1][t][c] + part[2][t][c] + part[3][t][c];
        }
    } else {
        // ---- embedding: 4 nodes per block ----
        __shared__ float sf[4][FEATD];
        int l = tid >> 6;
        int o = tid & 63;
        int node = (blockIdx.x - 64) * 4 + l;
        if (o < FEATD) sf[l][o] = feat[node * FEATD + o];
        __syncthreads();
        int t = ntype[node];
        float acc = b_emb[o] + W_emb[t * HH + o];
#pragma unroll
        for (int f = 0; f < FEATD; f++)
            acc += sf[l][f] * W_emb[(NTYPES + f) * HH + o];
        g_hA[node * HH + o] = acc;
    }
}

// ======== root transform, register-tiled: 64 nodes/block, 4x4 tiles ========
__global__ __launch_bounds__(256) void k_root(int flip, int iter,
                                              const float* __restrict__ roots,
                                              const float* __restrict__ bias) {
    const float* hin = flip ? g_hB : g_hA;
    float* hout      = flip ? g_hA : g_hB;

    __shared__ float hsT[HH][68];   // [k][node]
    __shared__ float Rs[HH * HH];   // [k*64+o]

    int tid = threadIdx.x;
    int base = blockIdx.x * 64;

    // load R (16KB, coalesced)
    const float* R = roots + iter * HH * HH;
    for (int i = tid; i < HH * HH; i += 256)
        Rs[i] = R[i];

    // gather 64 node rows, transpose to k-major
    {
        int l = tid >> 2;           // 0..63 local node
        int q = tid & 3;
        int node = base + l;
        if (node < NN) {
            const float4* hr = (const float4*)(hin + node * HH + q * 16);
#pragma unroll
            for (int j = 0; j < 4; j++) {
                float4 v = hr[j];
                int k = q * 16 + j * 4;
                hsT[k + 0][l] = v.x;
                hsT[k + 1][l] = v.y;
                hsT[k + 2][l] = v.z;
                hsT[k + 3][l] = v.w;
            }
        } else {
#pragma unroll
            for (int j = 0; j < 4; j++) {
                int k = q * 16 + j * 4;
                hsT[k + 0][l] = 0.f; hsT[k + 1][l] = 0.f;
                hsT[k + 2][l] = 0.f; hsT[k + 3][l] = 0.f;
            }
        }
    }
    __syncthreads();

    int ng = tid >> 4;   // 0..15 node group
    int og = tid & 15;   // 0..15 out group
    float acc[4][4];
#pragma unroll
    for (int a = 0; a < 4; a++)
#pragma unroll
        for (int b = 0; b < 4; b++) acc[a][b] = 0.f;

#pragma unroll 8
    for (int k = 0; k < HH; k++) {
        float4 hv = *(const float4*)&hsT[k][ng * 4];
        float4 rv = *(const float4*)&Rs[k * HH + og * 4];
        acc[0][0] += hv.x * rv.x; acc[0][1] += hv.x * rv.y; acc[0][2] += hv.x * rv.z; acc[0][3] += hv.x * rv.w;
        acc[1][0] += hv.y * rv.x; acc[1][1] += hv.y * rv.y; acc[1][2] += hv.y * rv.z; acc[1][3] += hv.y * rv.w;
        acc[2][0] += hv.z * rv.x; acc[2][1] += hv.z * rv.y; acc[2][2] += hv.z * rv.z; acc[2][3] += hv.z * rv.w;
        acc[3][0] += hv.w * rv.x; acc[3][1] += hv.w * rv.y; acc[3][2] += hv.w * rv.z; acc[3][3] += hv.w * rv.w;
    }

    float4 bv = *(const float4*)(bias + iter * HH + og * 4);
#pragma unroll
    for (int a = 0; a < 4; a++) {
        int node = base + ng * 4 + a;
        if (node < NN) {
            float4 o4;
            o4.x = acc[a][0] + bv.x;
            o4.y = acc[a][1] + bv.y;
            o4.z = acc[a][2] + bv.z;
            o4.w = acc[a][3] + bv.w;
            *(float4*)(hout + node * HH + og * 4) = o4;
        }
    }
}

// ======== type-grouped edge GEMM: 128 edges/block, 8x8 register tiles ======
__global__ __launch_bounds__(128) void k_edge(int flip) {
    const float* hin = flip ? g_hB : g_hA;
    float* hout      = flip ? g_hA : g_hB;

    __shared__ float hsT[HH][136];  // [k][edge], padded
    __shared__ float ws[HH * HH];   // [k*64+o]
    __shared__ int   ssrc[TE];
    __shared__ int   sdst[TE];

    int bid = blockIdx.x;
    if (bid >= g_tileoff[EDIM]) return;

    int t = 0;
    while (bid >= g_tileoff[t + 1]) t++;
    int tile = bid - g_tileoff[t];
    int base = g_toff[t] + tile * TE;
    int hi = g_toff[t + 1];

    int tid = threadIdx.x;

    // edge metadata (thread tid handles edge tid)
    {
        int p = base + tid;
        if (p < hi) { ssrc[tid] = g_psrc[p]; sdst[tid] = g_pdst[p]; }
        else        { ssrc[tid] = 0;         sdst[tid] = -1; }
    }

    // W tile (16KB, coalesced)
    const float* W = g_Wmat + t * HH * HH;
    for (int i = tid; i < HH * HH; i += 128)
        ws[i] = W[i];

    // gather own edge's h row, transpose to k-major (own ssrc -> no sync yet)
    {
        int s = ssrc[tid];
        const float4* hr = (const float4*)(hin + s * HH);
#pragma unroll
        for (int j = 0; j < 16; j++) {
            float4 v = hr[j];
            int k = j * 4;
            hsT[k + 0][tid] = v.x;
            hsT[k + 1][tid] = v.y;
            hsT[k + 2][tid] = v.z;
            hsT[k + 3][tid] = v.w;
        }
    }
    __syncthreads();

    int eg = tid >> 3;   // 0..15 edge group (8 edges)
    int og = tid & 7;    // 0..7  out group (8 outs)
    float acc[8][8];
#pragma unroll
    for (int a = 0; a < 8; a++)
#pragma unroll
        for (int b = 0; b < 8; b++) acc[a][b] = 0.f;

#pragma unroll 8
    for (int k = 0; k < HH; k++) {
        float4 h0 = *(const float4*)&hsT[k][eg * 8];
        float4 h1 = *(const float4*)&hsT[k][eg * 8 + 4];
        float4 w0 = *(const float4*)&ws[k * HH + og * 8];
        float4 w1 = *(const float4*)&ws[k * HH + og * 8 + 4];
        float hh[8] = {h0.x, h0.y, h0.z, h0.w, h1.x, h1.y, h1.z, h1.w};
        float wwv[8] = {w0.x, w0.y, w0.z, w0.w, w1.x, w1.y, w1.z, w1.w};
#pragma unroll
        for (int a = 0; a < 8; a++)
#pragma unroll
            for (int b = 0; b < 8; b++)
                acc[a][b] += hh[a] * wwv[b];
    }

#pragma unroll
    for (int a = 0; a < 8; a++) {
        int le = eg * 8 + a;
        int d = sdst[le];
        if (d >= 0) {
            float* dr = hout + d * HH + og * 8;
#pragma unroll
            for (int b = 0; b < 8; b++)
                atomicAdd(dr + b, acc[a][b]);
        }
    }
}

// ======== fused Set2Set iteration: LSTM cell + attention (+ final MLP) =====
__global__ __launch_bounds__(256) void k_s2s(const float* __restrict__ W_ih,
                                             const float* __restrict__ W_hh,
                                             const float* __restrict__ b_ih,
                                             const float* __restrict__ b_hh,
                                             int final_iter,
                                             const float* __restrict__ W_o1,
                                             const float* __restrict__ b_o1,
                                             const float* __restrict__ W_o2,
                                             const float* __restrict__ b_o2,
                                             float* __restrict__ out) {
    const float* h = g_hB;          // final node states after MPI=3
    int b = blockIdx.x;
    int tid = threadIdx.x;          // 256

    __shared__ float qs[2 * HH];    // q_star input
    __shared__ float hs[HH];        // old hx
    __shared__ float gates[4 * HH];
    __shared__ float q[HH];         // new hx
    __shared__ float red[256];
    __shared__ float r4[4][HH];
    __shared__ float rvec[HH];

    if (tid < 2 * HH) qs[tid] = g_qstar[b * 2 * HH + tid];
    if (tid < HH) hs[tid] = g_hx[b * HH + tid];
    __syncthreads();

    // ---- LSTM gates (one gate element per thread) ----
    {
        float g = b_ih[tid] + b_hh[tid];
        const float* wi = W_ih + tid * 2 * HH;
#pragma unroll 8
        for (int k = 0; k < 2 * HH; k++) g += qs[k] * wi[k];
        const float* wh = W_hh + tid * HH;
#pragma unroll 8
        for (int k = 0; k < HH; k++) g += hs[k] * wh[k];
        gates[tid] = g;
    }
    __syncthreads();
    if (tid < HH) {
        float ig = gates[tid], fg = gates[HH + tid];
        float gg = gates[2 * HH + tid], og = gates[3 * HH + tid];
        float si = 1.f / (1.f + expf(-ig));
        float sf = 1.f / (1.f + expf(-fg));
        float so = 1.f / (1.f + expf(-og));
        float c = sf * g_cx[b * HH + tid] + si * tanhf(gg);
        g_cx[b * HH + tid] = c;
        float hx = so * tanhf(c);
        g_hx[b * HH + tid] = hx;
        q[tid] = hx;
    }
    __syncthreads();

    int s = g_seg[b], t = g_seg[b + 1];

    // ---- pass 1: e = <h, q>, max ----
    float lmax = -1e30f;
    const float4* q4 = (const float4*)q;
    for (int n = s + tid; n < t; n += 256) {
        const float4* hr = (const float4*)(h + n * HH);
        float e = 0.f;
#pragma unroll
        for (int k = 0; k < HH / 4; k++) {
            float4 hv = hr[k];
            float4 qv = q4[k];
            e += hv.x * qv.x + hv.y * qv.y + hv.z * qv.z + hv.w * qv.w;
        }
        g_e[n] = e;
        lmax = fmaxf(lmax, e);
    }
    red[tid] = lmax; __syncthreads();
    for (int w = 128; w > 0; w >>= 1) {
        if (tid < w) red[tid] = fmaxf(red[tid], red[tid + w]);
        __syncthreads();
    }
    float m = red[0];
    __syncthreads();

    // ---- pass 2: a = exp(e - m), sum ----
    float lsum = 0.f;
    for (int n = s + tid; n < t; n += 256) {
        float a = expf(g_e[n] - m);
        g_a[n] = a;
        lsum += a;
    }
    red[tid] = lsum; __syncthreads();
    for (int w = 128; w > 0; w >>= 1) {
        if (tid < w) red[tid] += red[tid + w];
        __syncthreads();
    }
    float denom = red[0];
    if (denom == 0.f) denom = 1.f;
    __syncthreads();

    // ---- pass 3: weighted sum, 4-way split over n ----
    {
        int part = tid >> 6;
        int o = tid & 63;
        float r = 0.f;
        for (int n = s + part; n < t; n += 4) r += g_a[n] * h[n * HH + o];
        r4[part][o] = r;
    }
    __syncthreads();
    if (tid < HH) {
        float r = (r4[0][tid] + r4[1][tid] + r4[2][tid] + r4[3][tid]) / denom;
        rvec[tid] = r;
        g_qstar[b * 2 * HH + tid]      = q[tid];
        g_qstar[b * 2 * HH + HH + tid] = r;
    }
    __syncthreads();

    // ---- final iteration: output MLP inline ----
    if (final_iter) {
        if (tid < HH) {
            float v = b_o1[tid];
#pragma unroll 8
            for (int k = 0; k < HH; k++) v += q[k] * W_o1[k * HH + tid];
#pragma unroll 8
            for (int k = 0; k < HH; k++) v += rvec[k] * W_o1[(HH + k) * HH + tid];
            v = fmaxf(v, 0.f);
            red[tid] = v * W_o2[tid];
        }
        __syncthreads();
        for (int w = 32; w > 0; w >>= 1) {
            if (tid < w) red[tid] += red[tid + w];
            __syncthreads();
        }
        if (tid == 0) out[b] = red[0] + b_o2[0];
    }
}

// ---------------------------------------------------------------------------
extern "C" void kernel_launch(void* const* d_in, const int* in_sizes, int n_in,
                              void* d_out, int out_size) {
    const float* node_feat = (const float*)d_in[0];
    const int*   node_type = (const int*)d_in[1];
    const int*   edge_index= (const int*)d_in[2];
    const int*   etype     = (const int*)d_in[3];
    const int*   batch     = (const int*)d_in[4];
    const float* W_emb     = (const float*)d_in[5];
    const float* b_emb     = (const float*)d_in[6];
    const float* W_e1      = (const float*)d_in[7];
    const float* b_e1      = (const float*)d_in[8];
    const float* W_e2      = (const float*)d_in[9];
    const float* b_e2      = (const float*)d_in[10];
    const float* roots     = (const float*)d_in[11];
    const float* conv_bias = (const float*)d_in[12];
    const float* W_ih      = (const float*)d_in[13];
    const float* W_hh      = (const float*)d_in[14];
    const float* b_ih      = (const float*)d_in[15];
    const float* b_hh      = (const float*)d_in[16];
    const float* W_o1      = (const float*)d_in[17];
    const float* b_o1      = (const float*)d_in[18];
    const float* W_o2      = (const float*)d_in[19];
    const float* b_o2      = (const float*)d_in[20];
    float* out = (float*)d_out;

    const int* src = edge_index;
    const int* dst = edge_index + EE;

    k_setup<<<(EE + 255) / 256, 256>>>(batch, etype);
    k_scatter<<<(EE + 255) / 256, 256>>>(etype, src, dst);
    k_embwmat<<<64 + NN / 4, 256>>>(W_e1, b_e1, W_e2, b_e2,
                                    node_feat, node_type, W_emb, b_emb);

    for (int i = 0; i < MPI; i++) {
        int flip = i & 1;              // 0: A->B, 1: B->A, 2: A->B (final in g_hB)
        k_root<<<(NN + 63) / 64, 256>>>(flip, i, roots, conv_bias);
        k_edge<<<MAXTILES, 128>>>(flip);
    }

    for (int s = 0; s < S2S; s++) {
        k_s2s<<<BB, 256>>>(W_ih, W_hh, b_ih, b_hh, (s == S2S - 1),
                           W_o1, b_o1, W_o2, b_o2, out);
    }
}

// round 7
// speedup vs baseline: 1.0939x; 1.0939x over previous
#include <cuda_runtime.h>

#define NN 20000
#define EE 50000
#define BB 128
#define HH 64
#define FEATD 28
#define NTYPES 100
#define EDIM 5
#define MPI 3
#define S2S 4

#define TE 128                      // edges per GEMM tile
#define MAXTILES (EE / TE + EDIM)   // worst-case tile count across types
#define NROOT (NN / 4)              // root blocks (4 nodes each) = 5000

// ---------------- scratch (device globals; no allocation allowed) ----------
__device__ float g_hA[NN * HH];
__device__ float g_hB[NN * HH];
__device__ float g_hC[NN * HH];
__device__ float g_Wmat[EDIM * HH * HH];
__device__ float g_hx[BB * HH];
__device__ float g_cx[BB * HH];
__device__ float g_qstar[BB * 2 * HH];
__device__ float g_e[NN];
__device__ float g_a[NN];
__device__ int   g_seg[BB + 1];
__device__ int   g_tcnt[EDIM];
__device__ int   g_tptr[EDIM];
__device__ int   g_toff[EDIM + 1];
__device__ int   g_tileoff[EDIM + 1];
__device__ int   g_psrc[EE];
__device__ int   g_pdst[EE];
__device__ int   g_done = 0;

__device__ __forceinline__ float* hsel(int id) {
    return id == 0 ? g_hA : (id == 1 ? g_hB : g_hC);
}

// ======== setup: init state + seg bounds + type hist + (last block) scan ===
__global__ void k_setup(const int* __restrict__ batch,
                        const int* __restrict__ etype) {
    __shared__ int sh[EDIM];
    int tid = threadIdx.x;
    int gid = blockIdx.x * blockDim.x + tid;

    if (tid < EDIM) sh[tid] = 0;

    if (gid < BB * HH) { g_hx[gid] = 0.f; g_cx[gid] = 0.f; }
    if (gid < BB * 2 * HH) g_qstar[gid] = 0.f;

    if (blockIdx.x == 0 && tid <= BB) {
        if (tid == BB) g_seg[BB] = NN;
        else {
            int lo = 0, hi = NN;
            while (lo < hi) {
                int mid = (lo + hi) >> 1;
                if (batch[mid] < tid) lo = mid + 1; else hi = mid;
            }
            g_seg[tid] = lo;
        }
    }
    __syncthreads();

    if (gid < EE) atomicAdd(&sh[etype[gid]], 1);
    __syncthreads();
    if (tid < EDIM) atomicAdd(&g_tcnt[tid], sh[tid]);
    __syncthreads();

    if (tid == 0) {
        __threadfence();
        int old = atomicAdd(&g_done, 1);
        if (old == (int)gridDim.x - 1) {
            int off = 0, toff = 0;
            for (int t = 0; t < EDIM; t++) {
                int n = atomicAdd(&g_tcnt[t], 0);
                g_toff[t] = off;
                g_tileoff[t] = toff;
                g_tptr[t] = off;
                off += n;
                toff += (n + TE - 1) / TE;
                g_tcnt[t] = 0;
            }
            g_toff[EDIM] = off;
            g_tileoff[EDIM] = toff;
            g_done = 0;
        }
    }
}

// ======== scatter edges into type-grouped psrc/pdst ========================
__global__ void k_scatter(const int* __restrict__ etype,
                          const int* __restrict__ src,
                          const int* __restrict__ dst) {
    int e = blockIdx.x * blockDim.x + threadIdx.x;
    if (e < EE) {
        int pos = atomicAdd(&g_tptr[etype[e]], 1);
        g_psrc[pos] = src[e];
        g_pdst[pos] = dst[e];
    }
}

// ======== fused: wmat (blocks 0..63) + embedding (+ zero g_hB) =============
__global__ void k_embwmat(const float* __restrict__ W_e1,
                          const float* __restrict__ b_e1,
                          const float* __restrict__ W_e2,
                          const float* __restrict__ b_e2,
                          const float* __restrict__ feat,
                          const int* __restrict__ ntype,
                          const float* __restrict__ W_emb,
                          const float* __restrict__ b_emb) {
    int tid = threadIdx.x;
    if (blockIdx.x < 64) {
        __shared__ float hr[EDIM][HH];
        __shared__ float part[4][EDIM][HH];
        if (tid < HH) {
#pragma unroll
            for (int t = 0; t < EDIM; t++)
                hr[t][tid] = fmaxf(W_e1[t * HH + tid] + b_e1[tid], 0.f);
        }
        __syncthreads();
        int jc = tid >> 6;
        int c = tid & 63;
        int idx = blockIdx.x * 64 + c;
        float a0 = 0.f, a1 = 0.f, a2 = 0.f, a3 = 0.f, a4 = 0.f;
#pragma unroll
        for (int jj = 0; jj < 16; jj++) {
            int j = jc * 16 + jj;
            float w = W_e2[j * (HH * HH) + idx];
            a0 += hr[0][j] * w;
            a1 += hr[1][j] * w;
            a2 += hr[2][j] * w;
            a3 += hr[3][j] * w;
            a4 += hr[4][j] * w;
        }
        part[jc][0][c] = a0; part[jc][1][c] = a1; part[jc][2][c] = a2;
        part[jc][3][c] = a3; part[jc][4][c] = a4;
        __syncthreads();
        if (jc == 0) {
            float bb = b_e2[idx];
#pragma unroll
            for (int t = 0; t < EDIM; t++)
                g_Wmat[t * HH * HH + idx] =
                    bb + part[0][t][c] + part[1][t][c] + part[2][t][c] + part[3][t][c];
        }
    } else {
        __shared__ float sf[4][FEATD];
        int blk = blockIdx.x - 64;            // 0..4999
        int l = tid >> 6;
        int o = tid & 63;
        int node = blk * 4 + l;
        // zero g_hB for the first MP iteration's atomic accumulation
        g_hB[blk * 256 + tid] = 0.f;
        if (o < FEATD) sf[l][o] = feat[node * FEATD + o];
        __syncthreads();
        int t = ntype[node];
        float acc = b_emb[o] + W_emb[t * HH + o];
#pragma unroll
        for (int f = 0; f < FEATD; f++)
            acc += sf[l][f] * W_emb[(NTYPES + f) * HH + o];
        g_hA[node * HH + o] = acc;
    }
}

// ======== fused message-passing iteration: root + edge + zero-next =========
// Blocks [0, NROOT): root transform (4 nodes each), atomicAdd into hout,
//                    plus each zeroes 256 floats of the zero-buffer.
// Blocks [NROOT, NROOT+tiles): type-grouped edge GEMM (128 edges, 8x4 tiles).
__global__ __launch_bounds__(256) void k_mp(int in_id, int out_id, int zero_id,
                                            int iter,
                                            const float* __restrict__ roots,
                                            const float* __restrict__ bias) {
    const float* hin = hsel(in_id);
    float* hout      = hsel(out_id);
    int tid = threadIdx.x;

    if (blockIdx.x < NROOT) {
        // ---------------- root: 4 nodes per block ----------------
        __shared__ float sh[4][HH];
        int l = tid >> 6;
        int o = tid & 63;
        int node = blockIdx.x * 4 + l;
        if (zero_id >= 0)
            hsel(zero_id)[blockIdx.x * 256 + tid] = 0.f;   // NROOT*256 == NN*HH
        sh[l][o] = hin[node * HH + o];
        __syncthreads();
        const float* R = roots + iter * HH * HH;
        float acc = bias[iter * HH + o];
#pragma unroll
        for (int k = 0; k < HH; k++)
            acc += sh[l][k] * R[k * HH + o];
        atomicAdd(&hout[node * HH + o], acc);
    } else {
        // ---------------- edge GEMM tile ----------------
        __shared__ float hsT[HH][TE + 8];   // [k][edge]
        __shared__ float ws[HH * HH];       // [k*64+o]
        __shared__ int   ssrc[TE];
        __shared__ int   sdst[TE];

        int tb = blockIdx.x - NROOT;
        if (tb >= g_tileoff[EDIM]) return;

        int t = 0;
        while (tb >= g_tileoff[t + 1]) t++;
        int base = g_toff[t] + (tb - g_tileoff[t]) * TE;
        int hi = g_toff[t + 1];

        if (tid < TE) {
            int p = base + tid;
            if (p < hi) { ssrc[tid] = g_psrc[p]; sdst[tid] = g_pdst[p]; }
            else        { ssrc[tid] = 0;         sdst[tid] = -1; }
        }

        const float* W = g_Wmat + t * HH * HH;
        for (int i = tid; i < HH * HH; i += 256)
            ws[i] = W[i];
        __syncthreads();

        // gather: 2 threads per edge, each 32 floats, transpose to k-major
        {
            int e = tid >> 1;
            int half = tid & 1;
            int s = ssrc[e];
            const float4* hr = (const float4*)(hin + s * HH + half * 32);
#pragma unroll
            for (int j = 0; j < 8; j++) {
                float4 v = hr[j];
                int k = half * 32 + j * 4;
                hsT[k + 0][e] = v.x;
                hsT[k + 1][e] = v.y;
                hsT[k + 2][e] = v.z;
                hsT[k + 3][e] = v.w;
            }
        }
        __syncthreads();

        int eg = tid >> 4;   // 0..15 edge group (8 edges)
        int og = tid & 15;   // 0..15 out group (4 outs)
        float acc[8][4];
#pragma unroll
        for (int a = 0; a < 8; a++)
#pragma unroll
            for (int b = 0; b < 4; b++) acc[a][b] = 0.f;

#pragma unroll 8
        for (int k = 0; k < HH; k++) {
            float4 h0 = *(const float4*)&hsT[k][eg * 8];
            float4 h1 = *(const float4*)&hsT[k][eg * 8 + 4];
            float4 wv = *(const float4*)&ws[k * HH + og * 4];
            acc[0][0] += h0.x * wv.x; acc[0][1] += h0.x * wv.y; acc[0][2] += h0.x * wv.z; acc[0][3] += h0.x * wv.w;
            acc[1][0] += h0.y * wv.x; acc[1][1] += h0.y * wv.y; acc[1][2] += h0.y * wv.z; acc[1][3] += h0.y * wv.w;
            acc[2][0] += h0.z * wv.x; acc[2][1] += h0.z * wv.y; acc[2][2] += h0.z * wv.z; acc[2][3] += h0.z * wv.w;
            acc[3][0] += h0.w * wv.x; acc[3][1] += h0.w * wv.y; acc[3][2] += h0.w * wv.z; acc[3][3] += h0.w * wv.w;
            acc[4][0] += h1.x * wv.x; acc[4][1] += h1.x * wv.y; acc[4][2] += h1.x * wv.z; acc[4][3] += h1.x * wv.w;
            acc[5][0] += h1.y * wv.x; acc[5][1] += h1.y * wv.y; acc[5][2] += h1.y * wv.z; acc[5][3] += h1.y * wv.w;
            acc[6][0] += h1.z * wv.x; acc[6][1] += h1.z * wv.y; acc[6][2] += h1.z * wv.z; acc[6][3] += h1.z * wv.w;
            acc[7][0] += h1.w * wv.x; acc[7][1] += h1.w * wv.y; acc[7][2] += h1.w * wv.z; acc[7][3] += h1.w * wv.w;
        }

#pragma unroll
        for (int a = 0; a < 8; a++) {
            int d = sdst[eg * 8 + a];
            if (d >= 0) {
                float* dr = hout + d * HH + og * 4;
                atomicAdd(dr + 0, acc[a][0]);
                atomicAdd(dr + 1, acc[a][1]);
                atomicAdd(dr + 2, acc[a][2]);
                atomicAdd(dr + 3, acc[a][3]);
            }
        }
    }
}

// ======== fused Set2Set iteration: LSTM cell + attention (+ final MLP) =====
__global__ __launch_bounds__(256) void k_s2s(const float* __restrict__ W_ih,
                                             const float* __restrict__ W_hh,
                                             const float* __restrict__ b_ih,
                                             const float* __restrict__ b_hh,
                                             int final_iter,
                                             const float* __restrict__ W_o1,
                                             const float* __restrict__ b_o1,
                                             const float* __restrict__ W_o2,
                                             const float* __restrict__ b_o2,
                                             float* __restrict__ out) {
    const float* h = g_hA;          // final node states after MPI=3 (A<-C<-B<-A)
    int b = blockIdx.x;
    int tid = threadIdx.x;

    __shared__ float qs[2 * HH];
    __shared__ float hs[HH];
    __shared__ float gates[4 * HH];
    __shared__ float q[HH];
    __shared__ float red[256];
    __shared__ float r4[4][HH];
    __shared__ float rvec[HH];

    if (tid < 2 * HH) qs[tid] = g_qstar[b * 2 * HH + tid];
    if (tid < HH) hs[tid] = g_hx[b * HH + tid];
    __syncthreads();

    {
        float g = b_ih[tid] + b_hh[tid];
        const float* wi = W_ih + tid * 2 * HH;
#pragma unroll 8
        for (int k = 0; k < 2 * HH; k++) g += qs[k] * wi[k];
        const float* wh = W_hh + tid * HH;
#pragma unroll 8
        for (int k = 0; k < HH; k++) g += hs[k] * wh[k];
        gates[tid] = g;
    }
    __syncthreads();
    if (tid < HH) {
        float ig = gates[tid], fg = gates[HH + tid];
        float gg = gates[2 * HH + tid], og = gates[3 * HH + tid];
        float si = 1.f / (1.f + expf(-ig));
        float sf = 1.f / (1.f + expf(-fg));
        float so = 1.f / (1.f + expf(-og));
        float c = sf * g_cx[b * HH + tid] + si * tanhf(gg);
        g_cx[b * HH + tid] = c;
        float hx = so * tanhf(c);
        g_hx[b * HH + tid] = hx;
        q[tid] = hx;
    }
    __syncthreads();

    int s = g_seg[b], t = g_seg[b + 1];

    float lmax = -1e30f;
    const float4* q4 = (const float4*)q;
    for (int n = s + tid; n < t; n += 256) {
        const float4* hr = (const float4*)(h + n * HH);
        float e = 0.f;
#pragma unroll
        for (int k = 0; k < HH / 4; k++) {
            float4 hv = hr[k];
            float4 qv = q4[k];
            e += hv.x * qv.x + hv.y * qv.y + hv.z * qv.z + hv.w * qv.w;
        }
        g_e[n] = e;
        lmax = fmaxf(lmax, e);
    }
    red[tid] = lmax; __syncthreads();
    for (int w = 128; w > 0; w >>= 1) {
        if (tid < w) red[tid] = fmaxf(red[tid], red[tid + w]);
        __syncthreads();
    }
    float m = red[0];
    __syncthreads();

    float lsum = 0.f;
    for (int n = s + tid; n < t; n += 256) {
        float a = expf(g_e[n] - m);
        g_a[n] = a;
        lsum += a;
    }
    red[tid] = lsum; __syncthreads();
    for (int w = 128; w > 0; w >>= 1) {
        if (tid < w) red[tid] += red[tid + w];
        __syncthreads();
    }
    float denom = red[0];
    if (denom == 0.f) denom = 1.f;
    __syncthreads();

    {
        int part = tid >> 6;
        int o = tid & 63;
        float r = 0.f;
        for (int n = s + part; n < t; n += 4) r += g_a[n] * h[n * HH + o];
        r4[part][o] = r;
    }
    __syncthreads();
    if (tid < HH) {
        float r = (r4[0][tid] + r4[1][tid] + r4[2][tid] + r4[3][tid]) / denom;
        rvec[tid] = r;
        g_qstar[b * 2 * HH + tid]      = q[tid];
        g_qstar[b * 2 * HH + HH + tid] = r;
    }
    __syncthreads();

    if (final_iter) {
        if (tid < HH) {
            float v = b_o1[tid];
#pragma unroll 8
            for (int k = 0; k < HH; k++) v += q[k] * W_o1[k * HH + tid];
#pragma unroll 8
            for (int k = 0; k < HH; k++) v += rvec[k] * W_o1[(HH + k) * HH + tid];
            v = fmaxf(v, 0.f);
            red[tid] = v * W_o2[tid];
        }
        __syncthreads();
        for (int w = 32; w > 0; w >>= 1) {
            if (tid < w) red[tid] += red[tid + w];
            __syncthreads();
        }
        if (tid == 0) out[b] = red[0] + b_o2[0];
    }
}

// ---------------------------------------------------------------------------
extern "C" void kernel_launch(void* const* d_in, const int* in_sizes, int n_in,
                              void* d_out, int out_size) {
    const float* node_feat = (const float*)d_in[0];
    const int*   node_type = (const int*)d_in[1];
    const int*   edge_index= (const int*)d_in[2];
    const int*   etype     = (const int*)d_in[3];
    const int*   batch     = (const int*)d_in[4];
    const float* W_emb     = (const float*)d_in[5];
    const float* b_emb     = (const float*)d_in[6];
    const float* W_e1      = (const float*)d_in[7];
    const float* b_e1      = (const float*)d_in[8];
    const float* W_e2      = (const float*)d_in[9];
    const float* b_e2      = (const float*)d_in[10];
    const float* roots     = (const float*)d_in[11];
    const float* conv_bias = (const float*)d_in[12];
    const float* W_ih      = (const float*)d_in[13];
    const float* W_hh      = (const float*)d_in[14];
    const float* b_ih      = (const float*)d_in[15];
    const float* b_hh      = (const float*)d_in[16];
    const float* W_o1      = (const float*)d_in[17];
    const float* b_o1      = (const float*)d_in[18];
    const float* W_o2      = (const float*)d_in[19];
    const float* b_o2      = (const float*)d_in[20];
    float* out = (float*)d_out;

    const int* src = edge_index;
    const int* dst = edge_index + EE;

    k_setup<<<(EE + 255) / 256, 256>>>(batch, etype);
    k_scatter<<<(EE + 255) / 256, 256>>>(etype, src, dst);
    k_embwmat<<<64 + NROOT, 256>>>(W_e1, b_e1, W_e2, b_e2,
                                   node_feat, node_type, W_emb, b_emb);

    // 3-buffer rotation: (in, out, zero)
    k_mp<<<NROOT + MAXTILES, 256>>>(0, 1, 2, 0, roots, conv_bias);  // A->B, zero C
    k_mp<<<NROOT + MAXTILES, 256>>>(1, 2, 0, 1, roots, conv_bias);  // B->C, zero A
    k_mp<<<NROOT + MAXTILES, 256>>>(2, 0, -1, 2, roots, conv_bias); // C->A

    for (int s = 0; s < S2S; s++) {
        k_s2s<<<BB, 256>>>(W_ih, W_hh, b_ih, b_hh, (s == S2S - 1),
                           W_o1, b_o1, W_o2, b_o2, out);
    }
}

// round 8
// speedup vs baseline: 1.2947x; 1.1836x over previous
#include <cuda_runtime.h>

#define NN 20000
#define EE 50000
#define BB 128
#define HH 64
#define FEATD 28
#define NTYPES 100
#define EDIM 5
#define MPI 3
#define S2S 4

#define TE 128                       // edges/nodes per GEMM tile
#define EDGETILES (EE / TE + EDIM)   // worst-case edge tile count = 395
#define ROOTTILES ((NN + TE - 1) / TE)  // 157
#define GRIDMP (ROOTTILES + EDGETILES)
#define ZTOT (NN * HH / 4)           // float4 count of one h buffer

// ---------------- scratch (device globals; no allocation allowed) ----------
__device__ float g_hA[NN * HH];
__device__ float g_hB[NN * HH];
__device__ float g_hC[NN * HH];
__device__ float g_Wmat[EDIM * HH * HH];
__device__ float g_hx[BB * HH];
__device__ float g_cx[BB * HH];
__device__ float g_qstar[BB * 2 * HH];
__device__ float g_e[NN];
__device__ float g_a[NN];
__device__ int   g_seg[BB + 1];
__device__ int   g_tcnt[EDIM];
__device__ int   g_tptr[EDIM];
__device__ int   g_toff[EDIM + 1];
__device__ int   g_tileoff[EDIM + 1];
__device__ int   g_psrc[EE];
__device__ int   g_pdst[EE];
__device__ int   g_done = 0;

__device__ __forceinline__ float* hsel(int id) {
    return id == 0 ? g_hA : (id == 1 ? g_hB : g_hC);
}

__device__ __forceinline__ void red_v4(float* p, float a, float b, float c, float d) {
    asm volatile("red.global.add.v4.f32 [%0], {%1, %2, %3, %4};"
                 :: "l"(p), "f"(a), "f"(b), "f"(c), "f"(d) : "memory");
}

// ======== setup: init state + seg bounds + type hist + (last block) scan ===
__global__ void k_setup(const int* __restrict__ batch,
                        const int* __restrict__ etype) {
    __shared__ int sh[EDIM];
    int tid = threadIdx.x;
    int gid = blockIdx.x * blockDim.x + tid;

    if (tid < EDIM) sh[tid] = 0;

    if (gid < BB * HH) { g_hx[gid] = 0.f; g_cx[gid] = 0.f; }
    if (gid < BB * 2 * HH) g_qstar[gid] = 0.f;

    if (blockIdx.x == 0 && tid <= BB) {
        if (tid == BB) g_seg[BB] = NN;
        else {
            int lo = 0, hi = NN;
            while (lo < hi) {
                int mid = (lo + hi) >> 1;
                if (batch[mid] < tid) lo = mid + 1; else hi = mid;
            }
            g_seg[tid] = lo;
        }
    }
    __syncthreads();

    if (gid < EE) atomicAdd(&sh[etype[gid]], 1);
    __syncthreads();
    if (tid < EDIM) atomicAdd(&g_tcnt[tid], sh[tid]);
    __syncthreads();

    if (tid == 0) {
        __threadfence();
        int old = atomicAdd(&g_done, 1);
        if (old == (int)gridDim.x - 1) {
            int off = 0, toff = 0;
            for (int t = 0; t < EDIM; t++) {
                int n = atomicAdd(&g_tcnt[t], 0);
                g_toff[t] = off;
                g_tileoff[t] = toff;
                g_tptr[t] = off;
                off += n;
                toff += (n + TE - 1) / TE;
                g_tcnt[t] = 0;
            }
            g_toff[EDIM] = off;
            g_tileoff[EDIM] = toff;
            g_done = 0;
        }
    }
}

// ======== scatter edges into type-grouped psrc/pdst ========================
__global__ void k_scatter(const int* __restrict__ etype,
                          const int* __restrict__ src,
                          const int* __restrict__ dst) {
    int e = blockIdx.x * blockDim.x + threadIdx.x;
    if (e < EE) {
        int pos = atomicAdd(&g_tptr[etype[e]], 1);
        g_psrc[pos] = src[e];
        g_pdst[pos] = dst[e];
    }
}

// ======== fused: wmat (blocks 0..63) + embedding (+ zero g_hB) =============
__global__ void k_embwmat(const float* __restrict__ W_e1,
                          const float* __restrict__ b_e1,
                          const float* __restrict__ W_e2,
                          const float* __restrict__ b_e2,
                          const float* __restrict__ feat,
                          const int* __restrict__ ntype,
                          const float* __restrict__ W_emb,
                          const float* __restrict__ b_emb) {
    int tid = threadIdx.x;
    if (blockIdx.x < 64) {
        __shared__ float hr[EDIM][HH];
        __shared__ float part[4][EDIM][HH];
        if (tid < HH) {
#pragma unroll
            for (int t = 0; t < EDIM; t++)
                hr[t][tid] = fmaxf(W_e1[t * HH + tid] + b_e1[tid], 0.f);
        }
        __syncthreads();
        int jc = tid >> 6;
        int c = tid & 63;
        int idx = blockIdx.x * 64 + c;
        float a0 = 0.f, a1 = 0.f, a2 = 0.f, a3 = 0.f, a4 = 0.f;
#pragma unroll
        for (int jj = 0; jj < 16; jj++) {
            int j = jc * 16 + jj;
            float w = W_e2[j * (HH * HH) + idx];
            a0 += hr[0][j] * w;
            a1 += hr[1][j] * w;
            a2 += hr[2][j] * w;
            a3 += hr[3][j] * w;
            a4 += hr[4][j] * w;
        }
        part[jc][0][c] = a0; part[jc][1][c] = a1; part[jc][2][c] = a2;
        part[jc][3][c] = a3; part[jc][4][c] = a4;
        __syncthreads();
        if (jc == 0) {
            float bb = b_e2[idx];
#pragma unroll
            for (int t = 0; t < EDIM; t++)
                g_Wmat[t * HH * HH + idx] =
                    bb + part[0][t][c] + part[1][t][c] + part[2][t][c] + part[3][t][c];
        }
    } else {
        __shared__ float sf[4][FEATD];
        int blk = blockIdx.x - 64;            // 0..4999
        int l = tid >> 6;
        int o = tid & 63;
        int node = blk * 4 + l;
        // zero g_hB for the first MP iteration's atomic accumulation
        g_hB[blk * 256 + tid] = 0.f;
        if (o < FEATD) sf[l][o] = feat[node * FEATD + o];
        __syncthreads();
        int t = ntype[node];
        float acc = b_emb[o] + W_emb[t * HH + o];
#pragma unroll
        for (int f = 0; f < FEATD; f++)
            acc += sf[l][f] * W_emb[(NTYPES + f) * HH + o];
        g_hA[node * HH + o] = acc;
    }
}

// ======== fused MP iteration: root GEMM tiles + edge GEMM tiles + zero =====
// Blocks [0, ROOTTILES): 128 consecutive nodes, W = roots[iter], bias folded,
//                        "src = dst = node".
// Blocks [ROOTTILES, ...): type-grouped edge tiles (128 edges).
// All blocks first zero a grid-strided slice of the zero-buffer.
__global__ __launch_bounds__(256) void k_mp(int in_id, int out_id, int zero_id,
                                            int iter,
                                            const float* __restrict__ roots,
                                            const float* __restrict__ bias) {
    const float* hin = hsel(in_id);
    float* hout      = hsel(out_id);
    int tid = threadIdx.x;

    // ---- zero slice of next buffer (all blocks, before any return) ----
    if (zero_id >= 0) {
        float4* z = (float4*)hsel(zero_id);
        const int chunk = (ZTOT + GRIDMP - 1) / GRIDMP;   // float4s per block
        int lo = blockIdx.x * chunk;
        int hiz = lo + chunk; if (hiz > ZTOT) hiz = ZTOT;
        for (int i = lo + tid; i < hiz; i += 256)
            z[i] = make_float4(0.f, 0.f, 0.f, 0.f);
    }

    __shared__ float hsT[HH][TE + 8];   // [k][row]
    __shared__ float ws[HH * HH];       // [k*64+o]
    __shared__ int   sdst[TE];

    bool is_root = blockIdx.x < (unsigned)ROOTTILES;
    const float* W;
    int base;

    if (is_root) {
        base = blockIdx.x * TE;          // node base
        W = roots + iter * HH * HH;
        if (tid < TE) {
            int node = base + tid;
            sdst[tid] = (node < NN) ? node : -1;
        }
    } else {
        int tb = blockIdx.x - ROOTTILES;
        if (tb >= g_tileoff[EDIM]) return;
        int t = 0;
        while (tb >= g_tileoff[t + 1]) t++;
        base = g_toff[t] + (tb - g_tileoff[t]) * TE;
        int hi = g_toff[t + 1];
        W = g_Wmat + t * HH * HH;
        if (tid < TE) {
            int p = base + tid;
            sdst[tid] = (p < hi) ? g_pdst[p] : -1;
        }
    }

    // stage W (16KB, coalesced)
    for (int i = tid; i < HH * HH; i += 256)
        ws[i] = W[i];

    // gather rows, transpose to k-major: 2 threads per row, 32 floats each
    {
        int e = tid >> 1;
        int half = tid & 1;
        int s;
        if (is_root) {
            int node = base + e;
            s = (node < NN) ? node : 0;
        } else {
            int p = base + e;
            s = (sdst[e] >= 0) ? g_psrc[p] : 0;
        }
        const float4* hr = (const float4*)(hin + s * HH + half * 32);
#pragma unroll
        for (int j = 0; j < 8; j++) {
            float4 v = hr[j];
            int k = half * 32 + j * 4;
            hsT[k + 0][e] = v.x;
            hsT[k + 1][e] = v.y;
            hsT[k + 2][e] = v.z;
            hsT[k + 3][e] = v.w;
        }
    }
    __syncthreads();

    int eg = tid >> 4;   // 0..15 row group (8 rows)
    int og = tid & 15;   // 0..15 out group (4 outs)

    float acc[8][4];
    if (is_root) {
        float4 bv = *(const float4*)(bias + iter * HH + og * 4);
#pragma unroll
        for (int a = 0; a < 8; a++) {
            acc[a][0] = bv.x; acc[a][1] = bv.y; acc[a][2] = bv.z; acc[a][3] = bv.w;
        }
    } else {
#pragma unroll
        for (int a = 0; a < 8; a++)
#pragma unroll
            for (int b = 0; b < 4; b++) acc[a][b] = 0.f;
    }

#pragma unroll 8
    for (int k = 0; k < HH; k++) {
        float4 h0 = *(const float4*)&hsT[k][eg * 8];
        float4 h1 = *(const float4*)&hsT[k][eg * 8 + 4];
        float4 wv = *(const float4*)&ws[k * HH + og * 4];
        acc[0][0] += h0.x * wv.x; acc[0][1] += h0.x * wv.y; acc[0][2] += h0.x * wv.z; acc[0][3] += h0.x * wv.w;
        acc[1][0] += h0.y * wv.x; acc[1][1] += h0.y * wv.y; acc[1][2] += h0.y * wv.z; acc[1][3] += h0.y * wv.w;
        acc[2][0] += h0.z * wv.x; acc[2][1] += h0.z * wv.y; acc[2][2] += h0.z * wv.z; acc[2][3] += h0.z * wv.w;
        acc[3][0] += h0.w * wv.x; acc[3][1] += h0.w * wv.y; acc[3][2] += h0.w * wv.z; acc[3][3] += h0.w * wv.w;
        acc[4][0] += h1.x * wv.x; acc[4][1] += h1.x * wv.y; acc[4][2] += h1.x * wv.z; acc[4][3] += h1.x * wv.w;
        acc[5][0] += h1.y * wv.x; acc[5][1] += h1.y * wv.y; acc[5][2] += h1.y * wv.z; acc[5][3] += h1.y * wv.w;
        acc[6][0] += h1.z * wv.x; acc[6][1] += h1.z * wv.y; acc[6][2] += h1.z * wv.z; acc[6][3] += h1.z * wv.w;
        acc[7][0] += h1.w * wv.x; acc[7][1] += h1.w * wv.y; acc[7][2] += h1.w * wv.z; acc[7][3] += h1.w * wv.w;
    }

#pragma unroll
    for (int a = 0; a < 8; a++) {
        int d = sdst[eg * 8 + a];
        if (d >= 0)
            red_v4(hout + d * HH + og * 4, acc[a][0], acc[a][1], acc[a][2], acc[a][3]);
    }
}

// ======== fused Set2Set iteration: LSTM cell + attention (+ final MLP) =====
__global__ __launch_bounds__(256) void k_s2s(const float* __restrict__ W_ih,
                                             const float* __restrict__ W_hh,
                                             const float* __restrict__ b_ih,
                                             const float* __restrict__ b_hh,
                                             int final_iter,
                                             const float* __restrict__ W_o1,
                                             const float* __restrict__ b_o1,
                                             const float* __restrict__ W_o2,
                                             const float* __restrict__ b_o2,
                                             float* __restrict__ out) {
    const float* h = g_hA;          // final node states after MPI=3 (A->B->C->A)
    int b = blockIdx.x;
    int tid = threadIdx.x;

    __shared__ float qs[2 * HH];
    __shared__ float hs[HH];
    __shared__ float gates[4 * HH];
    __shared__ float q[HH];
    __shared__ float red[256];
    __shared__ float r4[4][HH];
    __shared__ float rvec[HH];

    if (tid < 2 * HH) qs[tid] = g_qstar[b * 2 * HH + tid];
    if (tid < HH) hs[tid] = g_hx[b * HH + tid];
    __syncthreads();

    {
        float g = b_ih[tid] + b_hh[tid];
        const float* wi = W_ih + tid * 2 * HH;
#pragma unroll 8
        for (int k = 0; k < 2 * HH; k++) g += qs[k] * wi[k];
        const float* wh = W_hh + tid * HH;
#pragma unroll 8
        for (int k = 0; k < HH; k++) g += hs[k] * wh[k];
        gates[tid] = g;
    }
    __syncthreads();
    if (tid < HH) {
        float ig = gates[tid], fg = gates[HH + tid];
        float gg = gates[2 * HH + tid], og = gates[3 * HH + tid];
        float si = 1.f / (1.f + expf(-ig));
        float sf = 1.f / (1.f + expf(-fg));
        float so = 1.f / (1.f + expf(-og));
        float c = sf * g_cx[b * HH + tid] + si * tanhf(gg);
        g_cx[b * HH + tid] = c;
        float hx = so * tanhf(c);
        g_hx[b * HH + tid] = hx;
        q[tid] = hx;
    }
    __syncthreads();

    int s = g_seg[b], t = g_seg[b + 1];

    float lmax = -1e30f;
    const float4* q4 = (const float4*)q;
    for (int n = s + tid; n < t; n += 256) {
        const float4* hr = (const float4*)(h + n * HH);
        float e = 0.f;
#pragma unroll
        for (int k = 0; k < HH / 4; k++) {
            float4 hv = hr[k];
            float4 qv = q4[k];
            e += hv.x * qv.x + hv.y * qv.y + hv.z * qv.z + hv.w * qv.w;
        }
        g_e[n] = e;
        lmax = fmaxf(lmax, e);
    }
    red[tid] = lmax; __syncthreads();
    for (int w = 128; w > 0; w >>= 1) {
        if (tid < w) red[tid] = fmaxf(red[tid], red[tid + w]);
        __syncthreads();
    }
    float m = red[0];
    __syncthreads();

    float lsum = 0.f;
    for (int n = s + tid; n < t; n += 256) {
        float a = expf(g_e[n] - m);
        g_a[n] = a;
        lsum += a;
    }
    red[tid] = lsum; __syncthreads();
    for (int w = 128; w > 0; w >>= 1) {
        if (tid < w) red[tid] += red[tid + w];
        __syncthreads();
    }
    float denom = red[0];
    if (denom == 0.f) denom = 1.f;
    __syncthreads();

    {
        int part = tid >> 6;
        int o = tid & 63;
        float r = 0.f;
        for (int n = s + part; n < t; n += 4) r += g_a[n] * h[n * HH + o];
        r4[part][o] = r;
    }
    __syncthreads();
    if (tid < HH) {
        float r = (r4[0][tid] + r4[1][tid] + r4[2][tid] + r4[3][tid]) / denom;
        rvec[tid] = r;
        g_qstar[b * 2 * HH + tid]      = q[tid];
        g_qstar[b * 2 * HH + HH + tid] = r;
    }
    __syncthreads();

    if (final_iter) {
        if (tid < HH) {
            float v = b_o1[tid];
#pragma unroll 8
            for (int k = 0; k < HH; k++) v += q[k] * W_o1[k * HH + tid];
#pragma unroll 8
            for (int k = 0; k < HH; k++) v += rvec[k] * W_o1[(HH + k) * HH + tid];
            v = fmaxf(v, 0.f);
            red[tid] = v * W_o2[tid];
        }
        __syncthreads();
        for (int w = 32; w > 0; w >>= 1) {
            if (tid < w) red[tid] += red[tid + w];
            __syncthreads();
        }
        if (tid == 0) out[b] = red[0] + b_o2[0];
    }
}

// ---------------------------------------------------------------------------
extern "C" void kernel_launch(void* const* d_in, const int* in_sizes, int n_in,
                              void* d_out, int out_size) {
    const float* node_feat = (const float*)d_in[0];
    const int*   node_type = (const int*)d_in[1];
    const int*   edge_index= (const int*)d_in[2];
    const int*   etype     = (const int*)d_in[3];
    const int*   batch     = (const int*)d_in[4];
    const float* W_emb     = (const float*)d_in[5];
    const float* b_emb     = (const float*)d_in[6];
    const float* W_e1      = (const float*)d_in[7];
    const float* b_e1      = (const float*)d_in[8];
    const float* W_e2      = (const float*)d_in[9];
    const float* b_e2      = (const float*)d_in[10];
    const float* roots     = (const float*)d_in[11];
    const float* conv_bias = (const float*)d_in[12];
    const float* W_ih      = (const float*)d_in[13];
    const float* W_hh      = (const float*)d_in[14];
    const float* b_ih      = (const float*)d_in[15];
    const float* b_hh      = (const float*)d_in[16];
    const float* W_o1      = (const float*)d_in[17];
    const float* b_o1      = (const float*)d_in[18];
    const float* W_o2      = (const float*)d_in[19];
    const float* b_o2      = (const float*)d_in[20];
    float* out = (float*)d_out;

    const int* src = edge_index;
    const int* dst = edge_index + EE;

    k_setup<<<(EE + 255) / 256, 256>>>(batch, etype);
    k_scatter<<<(EE + 255) / 256, 256>>>(etype, src, dst);
    k_embwmat<<<64 + NN / 4, 256>>>(W_e1, b_e1, W_e2, b_e2,
                                    node_feat, node_type, W_emb, b_emb);

    // 3-buffer rotation: (in, out, zero)
    k_mp<<<GRIDMP, 256>>>(0, 1, 2, 0, roots, conv_bias);  // A->B, zero C
    k_mp<<<GRIDMP, 256>>>(1, 2, 0, 1, roots, conv_bias);  // B->C, zero A
    k_mp<<<GRIDMP, 256>>>(2, 0, -1, 2, roots, conv_bias); // C->A

    for (int s = 0; s < S2S; s++) {
        k_s2s<<<BB, 256>>>(W_ih, W_hh, b_ih, b_hh, (s == S2S - 1),
                           W_o1, b_o1, W_o2, b_o2, out);
    }
}

// round 9
// speedup vs baseline: 1.3209x; 1.0203x over previous
#include <cuda_runtime.h>

#define NN 20000
#define EE 50000
#define BB 128
#define HH 64
#define FEATD 28
#define NTYPES 100
#define EDIM 5
#define MPI 3
#define S2S 4

#define TE 128                       // edges/nodes per GEMM tile
#define EDGETILES (EE / TE + EDIM)   // worst-case edge tile count = 395
#define ROOTTILES ((NN + TE - 1) / TE)  // 157
#define GRIDMP (ROOTTILES + EDGETILES)
#define ZTOT (NN * HH / 4)           // float4 count of one h buffer
#define SMAX 160                     // cached h rows per graph in k_s2s_all

// ---------------- scratch (device globals; no allocation allowed) ----------
__device__ float g_hA[NN * HH];
__device__ float g_hB[NN * HH];
__device__ float g_hC[NN * HH];
__device__ float g_Wmat[EDIM * HH * HH];
__device__ float g_e[NN];
__device__ float g_a[NN];
__device__ int   g_seg[BB + 1];
__device__ int   g_tcnt[EDIM];
__device__ int   g_tptr[EDIM];
__device__ int   g_toff[EDIM + 1];
__device__ int   g_tileoff[EDIM + 1];
__device__ int   g_psrc[EE];
__device__ int   g_pdst[EE];
__device__ int   g_done = 0;

__device__ __forceinline__ float* hsel(int id) {
    return id == 0 ? g_hA : (id == 1 ? g_hB : g_hC);
}

__device__ __forceinline__ void red_v4(float* p, float a, float b, float c, float d) {
    asm volatile("red.global.add.v4.f32 [%0], {%1, %2, %3, %4};"
                 :: "l"(p), "f"(a), "f"(b), "f"(c), "f"(d) : "memory");
}

// ======== setup: seg bounds + type hist + (last block) scan ================
__global__ void k_setup(const int* __restrict__ batch,
                        const int* __restrict__ etype) {
    __shared__ int sh[EDIM];
    int tid = threadIdx.x;
    int gid = blockIdx.x * blockDim.x + tid;

    if (tid < EDIM) sh[tid] = 0;

    if (blockIdx.x == 0 && tid <= BB) {
        if (tid == BB) g_seg[BB] = NN;
        else {
            int lo = 0, hi = NN;
            while (lo < hi) {
                int mid = (lo + hi) >> 1;
                if (batch[mid] < tid) lo = mid + 1; else hi = mid;
            }
            g_seg[tid] = lo;
        }
    }
    __syncthreads();

    if (gid < EE) atomicAdd(&sh[etype[gid]], 1);
    __syncthreads();
    if (tid < EDIM) atomicAdd(&g_tcnt[tid], sh[tid]);
    __syncthreads();

    if (tid == 0) {
        __threadfence();
        int old = atomicAdd(&g_done, 1);
        if (old == (int)gridDim.x - 1) {
            int off = 0, toff = 0;
            for (int t = 0; t < EDIM; t++) {
                int n = atomicAdd(&g_tcnt[t], 0);
                g_toff[t] = off;
                g_tileoff[t] = toff;
                g_tptr[t] = off;
                off += n;
                toff += (n + TE - 1) / TE;
                g_tcnt[t] = 0;
            }
            g_toff[EDIM] = off;
            g_tileoff[EDIM] = toff;
            g_done = 0;
        }
    }
}

// ======== scatter edges into type-grouped psrc/pdst ========================
__global__ void k_scatter(const int* __restrict__ etype,
                          const int* __restrict__ src,
                          const int* __restrict__ dst) {
    int e = blockIdx.x * blockDim.x + threadIdx.x;
    if (e < EE) {
        int pos = atomicAdd(&g_tptr[etype[e]], 1);
        g_psrc[pos] = src[e];
        g_pdst[pos] = dst[e];
    }
}

// ======== fused: wmat (blocks 0..63) + embedding (+ zero g_hB) =============
__global__ void k_embwmat(const float* __restrict__ W_e1,
                          const float* __restrict__ b_e1,
                          const float* __restrict__ W_e2,
                          const float* __restrict__ b_e2,
                          const float* __restrict__ feat,
                          const int* __restrict__ ntype,
                          const float* __restrict__ W_emb,
                          const float* __restrict__ b_emb) {
    int tid = threadIdx.x;
    if (blockIdx.x < 64) {
        __shared__ float hr[EDIM][HH];
        __shared__ float part[4][EDIM][HH];
        if (tid < HH) {
#pragma unroll
            for (int t = 0; t < EDIM; t++)
                hr[t][tid] = fmaxf(W_e1[t * HH + tid] + b_e1[tid], 0.f);
        }
        __syncthreads();
        int jc = tid >> 6;
        int c = tid & 63;
        int idx = blockIdx.x * 64 + c;
        float a0 = 0.f, a1 = 0.f, a2 = 0.f, a3 = 0.f, a4 = 0.f;
#pragma unroll
        for (int jj = 0; jj < 16; jj++) {
            int j = jc * 16 + jj;
            float w = W_e2[j * (HH * HH) + idx];
            a0 += hr[0][j] * w;
            a1 += hr[1][j] * w;
            a2 += hr[2][j] * w;
            a3 += hr[3][j] * w;
            a4 += hr[4][j] * w;
        }
        part[jc][0][c] = a0; part[jc][1][c] = a1; part[jc][2][c] = a2;
        part[jc][3][c] = a3; part[jc][4][c] = a4;
        __syncthreads();
        if (jc == 0) {
            float bb = b_e2[idx];
#pragma unroll
            for (int t = 0; t < EDIM; t++)
                g_Wmat[t * HH * HH + idx] =
                    bb + part[0][t][c] + part[1][t][c] + part[2][t][c] + part[3][t][c];
        }
    } else {
        __shared__ float sf[4][FEATD];
        int blk = blockIdx.x - 64;            // 0..4999
        int l = tid >> 6;
        int o = tid & 63;
        int node = blk * 4 + l;
        // zero g_hB for the first MP iteration's atomic accumulation
        g_hB[blk * 256 + tid] = 0.f;
        if (o < FEATD) sf[l][o] = feat[node * FEATD + o];
        __syncthreads();
        int t = ntype[node];
        float acc = b_emb[o] + W_emb[t * HH + o];
#pragma unroll
        for (int f = 0; f < FEATD; f++)
            acc += sf[l][f] * W_emb[(NTYPES + f) * HH + o];
        g_hA[node * HH + o] = acc;
    }
}

// ======== fused MP iteration: root GEMM tiles + edge GEMM tiles + zero =====
__global__ __launch_bounds__(256) void k_mp(int in_id, int out_id, int zero_id,
                                            int iter,
                                            const float* __restrict__ roots,
                                            const float* __restrict__ bias) {
    const float* hin = hsel(in_id);
    float* hout      = hsel(out_id);
    int tid = threadIdx.x;

    // ---- zero slice of next buffer (all blocks, before any return) ----
    if (zero_id >= 0) {
        float4* z = (float4*)hsel(zero_id);
        const int chunk = (ZTOT + GRIDMP - 1) / GRIDMP;
        int lo = blockIdx.x * chunk;
        int hiz = lo + chunk; if (hiz > ZTOT) hiz = ZTOT;
        for (int i = lo + tid; i < hiz; i += 256)
            z[i] = make_float4(0.f, 0.f, 0.f, 0.f);
    }

    __shared__ float hsT[HH][TE + 8];   // [k][row]
    __shared__ float ws[HH * HH];       // [k*64+o]
    __shared__ int   sdst[TE];

    bool is_root = blockIdx.x < (unsigned)ROOTTILES;
    const float* W;
    int base;

    if (is_root) {
        base = blockIdx.x * TE;
        W = roots + iter * HH * HH;
        if (tid < TE) {
            int node = base + tid;
            sdst[tid] = (node < NN) ? node : -1;
        }
    } else {
        int tb = blockIdx.x - ROOTTILES;
        if (tb >= g_tileoff[EDIM]) return;
        int t = 0;
        while (tb >= g_tileoff[t + 1]) t++;
        base = g_toff[t] + (tb - g_tileoff[t]) * TE;
        int hi = g_toff[t + 1];
        W = g_Wmat + t * HH * HH;
        if (tid < TE) {
            int p = base + tid;
            sdst[tid] = (p < hi) ? g_pdst[p] : -1;
        }
    }

    for (int i = tid; i < HH * HH; i += 256)
        ws[i] = W[i];

    {
        int e = tid >> 1;
        int half = tid & 1;
        int s;
        if (is_root) {
            int node = base + e;
            s = (node < NN) ? node : 0;
        } else {
            int p = base + e;
            s = (sdst[e] >= 0) ? g_psrc[p] : 0;
        }
        const float4* hr = (const float4*)(hin + s * HH + half * 32);
#pragma unroll
        for (int j = 0; j < 8; j++) {
            float4 v = hr[j];
            int k = half * 32 + j * 4;
            hsT[k + 0][e] = v.x;
            hsT[k + 1][e] = v.y;
            hsT[k + 2][e] = v.z;
            hsT[k + 3][e] = v.w;
        }
    }
    __syncthreads();

    int eg = tid >> 4;
    int og = tid & 15;

    float acc[8][4];
    if (is_root) {
        float4 bv = *(const float4*)(bias + iter * HH + og * 4);
#pragma unroll
        for (int a = 0; a < 8; a++) {
            acc[a][0] = bv.x; acc[a][1] = bv.y; acc[a][2] = bv.z; acc[a][3] = bv.w;
        }
    } else {
#pragma unroll
        for (int a = 0; a < 8; a++)
#pragma unroll
            for (int b = 0; b < 4; b++) acc[a][b] = 0.f;
    }

#pragma unroll 8
    for (int k = 0; k < HH; k++) {
        float4 h0 = *(const float4*)&hsT[k][eg * 8];
        float4 h1 = *(const float4*)&hsT[k][eg * 8 + 4];
        float4 wv = *(const float4*)&ws[k * HH + og * 4];
        acc[0][0] += h0.x * wv.x; acc[0][1] += h0.x * wv.y; acc[0][2] += h0.x * wv.z; acc[0][3] += h0.x * wv.w;
        acc[1][0] += h0.y * wv.x; acc[1][1] += h0.y * wv.y; acc[1][2] += h0.y * wv.z; acc[1][3] += h0.y * wv.w;
        acc[2][0] += h0.z * wv.x; acc[2][1] += h0.z * wv.y; acc[2][2] += h0.z * wv.z; acc[2][3] += h0.z * wv.w;
        acc[3][0] += h0.w * wv.x; acc[3][1] += h0.w * wv.y; acc[3][2] += h0.w * wv.z; acc[3][3] += h0.w * wv.w;
        acc[4][0] += h1.x * wv.x; acc[4][1] += h1.x * wv.y; acc[4][2] += h1.x * wv.z; acc[4][3] += h1.x * wv.w;
        acc[5][0] += h1.y * wv.x; acc[5][1] += h1.y * wv.y; acc[5][2] += h1.y * wv.z; acc[5][3] += h1.y * wv.w;
        acc[6][0] += h1.z * wv.x; acc[6][1] += h1.z * wv.y; acc[6][2] += h1.z * wv.z; acc[6][3] += h1.z * wv.w;
        acc[7][0] += h1.w * wv.x; acc[7][1] += h1.w * wv.y; acc[7][2] += h1.w * wv.z; acc[7][3] += h1.w * wv.w;
    }

#pragma unroll
    for (int a = 0; a < 8; a++) {
        int d = sdst[eg * 8 + a];
        if (d >= 0)
            red_v4(hout + d * HH + og * 4, acc[a][0], acc[a][1], acc[a][2], acc[a][3]);
    }
}

// ======== fully fused Set2Set: 4 iterations + output MLP in one kernel =====
// One block per graph. LSTM state + q_star live in smem. The graph's h
// segment (up to SMAX rows) is cached in smem once and reused across all
// iterations; overflow rows stream from L2.
__global__ __launch_bounds__(256) void k_s2s_all(const float* __restrict__ W_ih,
                                                 const float* __restrict__ W_hh,
                                                 const float* __restrict__ b_ih,
                                                 const float* __restrict__ b_hh,
                                                 const float* __restrict__ W_o1,
                                                 const float* __restrict__ b_o1,
                                                 const float* __restrict__ W_o2,
                                                 const float* __restrict__ b_o2,
                                                 float* __restrict__ out) {
    const float* h = g_hA;          // final node states after MPI=3 (A->B->C->A)
    int b = blockIdx.x;
    int tid = threadIdx.x;

    __shared__ float hcache[SMAX * HH];   // 40KB
    __shared__ float qs[2 * HH];
    __shared__ float gates[4 * HH];
    __shared__ float q[HH];
    __shared__ float hx_s[HH];
    __shared__ float cx_s[HH];
    __shared__ float red[256];
    __shared__ float r4[4][HH];

    int s = g_seg[b], t = g_seg[b + 1];
    int len = t - s;
    int nc = len < SMAX ? len : SMAX;

    // cache segment h rows (coalesced float4 copy)
    {
        float4* d4 = (float4*)hcache;
        const float4* s4 = (const float4*)(h + s * HH);
        int tot = nc * (HH / 4);
        for (int i = tid; i < tot; i += 256) d4[i] = s4[i];
    }
    if (tid < 2 * HH) qs[tid] = 0.f;
    if (tid < HH) { hx_s[tid] = 0.f; cx_s[tid] = 0.f; }
    __syncthreads();

    for (int it = 0; it < S2S; it++) {
        // ---- LSTM gates ----
        {
            float g = b_ih[tid] + b_hh[tid];
            const float* wi = W_ih + tid * 2 * HH;
#pragma unroll 8
            for (int k = 0; k < 2 * HH; k++) g += qs[k] * wi[k];
            const float* wh = W_hh + tid * HH;
#pragma unroll 8
            for (int k = 0; k < HH; k++) g += hx_s[k] * wh[k];
            gates[tid] = g;
        }
        __syncthreads();
        if (tid < HH) {
            float ig = gates[tid], fg = gates[HH + tid];
            float gg = gates[2 * HH + tid], og = gates[3 * HH + tid];
            float si = 1.f / (1.f + expf(-ig));
            float sf = 1.f / (1.f + expf(-fg));
            float so = 1.f / (1.f + expf(-og));
            float c = sf * cx_s[tid] + si * tanhf(gg);
            cx_s[tid] = c;
            float hx = so * tanhf(c);
            hx_s[tid] = hx;
            q[tid] = hx;
        }
        __syncthreads();

        // ---- pass 1: e = <h, q>, max ----
        float lmax = -1e30f;
        const float4* q4 = (const float4*)q;
        for (int l = tid; l < len; l += 256) {
            const float4* hr = (l < nc) ? (const float4*)&hcache[l * HH]
                                        : (const float4*)(h + (s + l) * HH);
            float e = 0.f;
#pragma unroll
            for (int k = 0; k < HH / 4; k++) {
                float4 hv = hr[k];
                float4 qv = q4[k];
                e += hv.x * qv.x + hv.y * qv.y + hv.z * qv.z + hv.w * qv.w;
            }
            g_e[s + l] = e;
            lmax = fmaxf(lmax, e);
        }
        red[tid] = lmax; __syncthreads();
        for (int w = 128; w > 0; w >>= 1) {
            if (tid < w) red[tid] = fmaxf(red[tid], red[tid + w]);
            __syncthreads();
        }
        float m = red[0];
        __syncthreads();

        // ---- pass 2: a = exp(e - m), sum ----
        float lsum = 0.f;
        for (int l = tid; l < len; l += 256) {
            float a = expf(g_e[s + l] - m);
            g_a[s + l] = a;
            lsum += a;
        }
        red[tid] = lsum; __syncthreads();
        for (int w = 128; w > 0; w >>= 1) {
            if (tid < w) red[tid] += red[tid + w];
            __syncthreads();
        }
        float denom = red[0];
        if (denom == 0.f) denom = 1.f;
        __syncthreads();

        // ---- pass 3: r[o] = sum a*h / denom, 4-way n split ----
        {
            int part = tid >> 6;
            int o = tid & 63;
            float r = 0.f;
            for (int l = part; l < len; l += 4) {
                float hv = (l < nc) ? hcache[l * HH + o] : h[(s + l) * HH + o];
                r += g_a[s + l] * hv;
            }
            r4[part][o] = r;
        }
        __syncthreads();
        if (tid < HH) {
            float r = (r4[0][tid] + r4[1][tid] + r4[2][tid] + r4[3][tid]) / denom;
            qs[tid]      = q[tid];
            qs[HH + tid] = r;
        }
        __syncthreads();
    }

    // ---- output MLP: relu(q_star @ W_o1 + b_o1) @ W_o2 + b_o2 ----
    if (tid < HH) {
        float v = b_o1[tid];
#pragma unroll 8
        for (int k = 0; k < 2 * HH; k++) v += qs[k] * W_o1[k * HH + tid];
        v = fmaxf(v, 0.f);
        red[tid] = v * W_o2[tid];
    }
    __syncthreads();
    for (int w = 32; w > 0; w >>= 1) {
        if (tid < w) red[tid] += red[tid + w];
        __syncthreads();
    }
    if (tid == 0) out[b] = red[0] + b_o2[0];
}

// ---------------------------------------------------------------------------
extern "C" void kernel_launch(void* const* d_in, const int* in_sizes, int n_in,
                              void* d_out, int out_size) {
    const float* node_feat = (const float*)d_in[0];
    const int*   node_type = (const int*)d_in[1];
    const int*   edge_index= (const int*)d_in[2];
    const int*   etype     = (const int*)d_in[3];
    const int*   batch     = (const int*)d_in[4];
    const float* W_emb     = (const float*)d_in[5];
    const float* b_emb     = (const float*)d_in[6];
    const float* W_e1      = (const float*)d_in[7];
    const float* b_e1      = (const float*)d_in[8];
    const float* W_e2      = (const float*)d_in[9];
    const float* b_e2      = (const float*)d_in[10];
    const float* roots     = (const float*)d_in[11];
    const float* conv_bias = (const float*)d_in[12];
    const float* W_ih      = (const float*)d_in[13];
    const float* W_hh      = (const float*)d_in[14];
    const float* b_ih      = (const float*)d_in[15];
    const float* b_hh      = (const float*)d_in[16];
    const float* W_o1      = (const float*)d_in[17];
    const float* b_o1      = (const float*)d_in[18];
    const float* W_o2      = (const float*)d_in[19];
    const float* b_o2      = (const float*)d_in[20];
    float* out = (float*)d_out;

    const int* src = edge_index;
    const int* dst = edge_index + EE;

    k_setup<<<(EE + 255) / 256, 256>>>(batch, etype);
    k_scatter<<<(EE + 255) / 256, 256>>>(etype, src, dst);
    k_embwmat<<<64 + NN / 4, 256>>>(W_e1, b_e1, W_e2, b_e2,
                                    node_feat, node_type, W_emb, b_emb);

    // 3-buffer rotation: (in, out, zero)
    k_mp<<<GRIDMP, 256>>>(0, 1, 2, 0, roots, conv_bias);  // A->B, zero C
    k_mp<<<GRIDMP, 256>>>(1, 2, 0, 1, roots, conv_bias);  // B->C, zero A
    k_mp<<<GRIDMP, 256>>>(2, 0, -1, 2, roots, conv_bias); // C->A

    k_s2s_all<<<BB, 256>>>(W_ih, W_hh, b_ih, b_hh,
                           W_o1, b_o1, W_o2, b_o2, out);
}

// round 10
// speedup vs baseline: 1.3479x; 1.0204x over previous
#include <cuda_runtime.h>

#define NN 20000
#define EE 50000
#define BB 128
#define HH 64
#define FEATD 28
#define NTYPES 100
#define EDIM 5
#define MPI 3
#define S2S 4

#define TE 128                       // edges/nodes per GEMM tile
#define EDGETILES (EE / TE + EDIM)   // worst-case edge tile count = 395
#define ROOTTILES ((NN + TE - 1) / TE)  // 157
#define GRIDMP (ROOTTILES + EDGETILES)
#define ZTOT (NN * HH / 4)           // float4 count of one h buffer
#define SMAX 160                     // cached h rows per graph in k_s2s_all
#define SCB ((EE + 255) / 256)       // scatter blocks in fused kernel

// ---------------- scratch (device globals; no allocation allowed) ----------
__device__ float g_hA[NN * HH];
__device__ float g_hB[NN * HH];
__device__ float g_hC[NN * HH];
__device__ float g_Wmat[EDIM * HH * HH];
__device__ float g_e[NN];
__device__ float g_a[NN];
__device__ int   g_seg[BB + 1];
__device__ int   g_tcnt[EDIM];
__device__ int   g_tptr[EDIM];
__device__ int   g_toff[EDIM + 1];
__device__ int   g_tileoff[EDIM + 1];
__device__ int   g_psrc[EE];
__device__ int   g_pdst[EE];
__device__ int   g_done = 0;

__device__ __forceinline__ float* hsel(int id) {
    return id == 0 ? g_hA : (id == 1 ? g_hB : g_hC);
}

__device__ __forceinline__ void red_v4(float* p, float a, float b, float c, float d) {
    asm volatile("red.global.add.v4.f32 [%0], {%1, %2, %3, %4};"
                 :: "l"(p), "f"(a), "f"(b), "f"(c), "f"(d) : "memory");
}

// ======== setup: seg bounds + type hist + (last block) scan ================
__global__ void k_setup(const int* __restrict__ batch,
                        const int* __restrict__ etype) {
    __shared__ int sh[EDIM];
    int tid = threadIdx.x;
    int gid = blockIdx.x * blockDim.x + tid;

    if (tid < EDIM) sh[tid] = 0;

    if (blockIdx.x == 0 && tid <= BB) {
        if (tid == BB) g_seg[BB] = NN;
        else {
            int lo = 0, hi = NN;
            while (lo < hi) {
                int mid = (lo + hi) >> 1;
                if (batch[mid] < tid) lo = mid + 1; else hi = mid;
            }
            g_seg[tid] = lo;
        }
    }
    __syncthreads();

    if (gid < EE) atomicAdd(&sh[etype[gid]], 1);
    __syncthreads();
    if (tid < EDIM) atomicAdd(&g_tcnt[tid], sh[tid]);
    __syncthreads();

    if (tid == 0) {
        __threadfence();
        int old = atomicAdd(&g_done, 1);
        if (old == (int)gridDim.x - 1) {
            int off = 0, toff = 0;
            for (int t = 0; t < EDIM; t++) {
                int n = atomicAdd(&g_tcnt[t], 0);
                g_toff[t] = off;
                g_tileoff[t] = toff;
                g_tptr[t] = off;
                off += n;
                toff += (n + TE - 1) / TE;
                g_tcnt[t] = 0;
            }
            g_toff[EDIM] = off;
            g_tileoff[EDIM] = toff;
            g_done = 0;
        }
    }
}

// ======== fused: scatter + wmat + embedding (+ zero g_hB) ==================
// Blocks [0, SCB): scatter edges into type-grouped psrc/pdst.
// Blocks [SCB, SCB+64): the 5 edge weight matrices.
// Blocks [SCB+64, ...): node embedding (4 nodes each) + zero g_hB slice.
__global__ void k_front(const int* __restrict__ etype,
                        const int* __restrict__ src,
                        const int* __restrict__ dst,
                        const float* __restrict__ W_e1,
                        const float* __restrict__ b_e1,
                        const float* __restrict__ W_e2,
                        const float* __restrict__ b_e2,
                        const float* __restrict__ feat,
                        const int* __restrict__ ntype,
                        const float* __restrict__ W_emb,
                        const float* __restrict__ b_emb) {
    int tid = threadIdx.x;
    if (blockIdx.x < SCB) {
        int e = blockIdx.x * 256 + tid;
        if (e < EE) {
            int pos = atomicAdd(&g_tptr[etype[e]], 1);
            g_psrc[pos] = src[e];
            g_pdst[pos] = dst[e];
        }
    } else if (blockIdx.x < SCB + 64) {
        __shared__ float hr[EDIM][HH];
        __shared__ float part[4][EDIM][HH];
        int wb = blockIdx.x - SCB;
        if (tid < HH) {
#pragma unroll
            for (int t = 0; t < EDIM; t++)
                hr[t][tid] = fmaxf(W_e1[t * HH + tid] + b_e1[tid], 0.f);
        }
        __syncthreads();
        int jc = tid >> 6;
        int c = tid & 63;
        int idx = wb * 64 + c;
        float a0 = 0.f, a1 = 0.f, a2 = 0.f, a3 = 0.f, a4 = 0.f;
#pragma unroll
        for (int jj = 0; jj < 16; jj++) {
            int j = jc * 16 + jj;
            float w = W_e2[j * (HH * HH) + idx];
            a0 += hr[0][j] * w;
            a1 += hr[1][j] * w;
            a2 += hr[2][j] * w;
            a3 += hr[3][j] * w;
            a4 += hr[4][j] * w;
        }
        part[jc][0][c] = a0; part[jc][1][c] = a1; part[jc][2][c] = a2;
        part[jc][3][c] = a3; part[jc][4][c] = a4;
        __syncthreads();
        if (jc == 0) {
            float bb = b_e2[idx];
#pragma unroll
            for (int t = 0; t < EDIM; t++)
                g_Wmat[t * HH * HH + idx] =
                    bb + part[0][t][c] + part[1][t][c] + part[2][t][c] + part[3][t][c];
        }
    } else {
        __shared__ float sf[4][FEATD];
        int blk = blockIdx.x - SCB - 64;      // 0..4999
        int l = tid >> 6;
        int o = tid & 63;
        int node = blk * 4 + l;
        // zero g_hB for the first MP iteration's atomic accumulation
        g_hB[blk * 256 + tid] = 0.f;
        if (o < FEATD) sf[l][o] = feat[node * FEATD + o];
        __syncthreads();
        int t = ntype[node];
        float acc = b_emb[o] + W_emb[t * HH + o];
#pragma unroll
        for (int f = 0; f < FEATD; f++)
            acc += sf[l][f] * W_emb[(NTYPES + f) * HH + o];
        g_hA[node * HH + o] = acc;
    }
}

// ======== fused MP iteration: root + edge GEMM tiles, 8x8 register tiles ===
// 128 threads/block; thread (rg = tid>>3, og = tid&7) computes rows
// rg*8..rg*8+7  x  outs og*8..og*8+7.  16 FMA per LDS.128.
__global__ __launch_bounds__(128) void k_mp(int in_id, int out_id, int zero_id,
                                            int iter,
                                            const float* __restrict__ roots,
                                            const float* __restrict__ bias) {
    const float* hin = hsel(in_id);
    float* hout      = hsel(out_id);
    int tid = threadIdx.x;

    // ---- zero slice of next buffer (all blocks, before any return) ----
    if (zero_id >= 0) {
        float4* z = (float4*)hsel(zero_id);
        const int chunk = (ZTOT + GRIDMP - 1) / GRIDMP;
        int lo = blockIdx.x * chunk;
        int hiz = lo + chunk; if (hiz > ZTOT) hiz = ZTOT;
        for (int i = lo + tid; i < hiz; i += 128)
            z[i] = make_float4(0.f, 0.f, 0.f, 0.f);
    }

    __shared__ float hsT[HH][TE + 8];   // [k][row]
    __shared__ float ws[HH * HH];       // [k*64+o]
    __shared__ int   sdst[TE];

    bool is_root = blockIdx.x < (unsigned)ROOTTILES;
    const float* W;
    int base;

    if (is_root) {
        base = blockIdx.x * TE;
        W = roots + iter * HH * HH;
        if (tid < TE) {
            int node = base + tid;
            sdst[tid] = (node < NN) ? node : -1;
        }
    } else {
        int tb = blockIdx.x - ROOTTILES;
        if (tb >= g_tileoff[EDIM]) return;
        int t = 0;
        while (tb >= g_tileoff[t + 1]) t++;
        base = g_toff[t] + (tb - g_tileoff[t]) * TE;
        int hi = g_toff[t + 1];
        W = g_Wmat + t * HH * HH;
        if (tid < TE) {
            int p = base + tid;
            sdst[tid] = (p < hi) ? g_pdst[p] : -1;
        }
    }

    // stage W (16KB, coalesced)
    for (int i = tid; i < HH * HH; i += 128)
        ws[i] = W[i];

    // gather: one thread per row, 64 floats, transpose to k-major
    {
        int s;
        if (is_root) {
            int node = base + tid;
            s = (node < NN) ? node : 0;
        } else {
            int p = base + tid;
            s = (sdst[tid] >= 0) ? g_psrc[p] : 0;
        }
        const float4* hr = (const float4*)(hin + s * HH);
#pragma unroll
        for (int j = 0; j < 16; j++) {
            float4 v = hr[j];
            int k = j * 4;
            hsT[k + 0][tid] = v.x;
            hsT[k + 1][tid] = v.y;
            hsT[k + 2][tid] = v.z;
            hsT[k + 3][tid] = v.w;
        }
    }
    __syncthreads();

    int rg = tid >> 3;   // 0..15 row group (8 rows)
    int og = tid & 7;    // 0..7  out group (8 outs)

    float acc[8][8];
    if (is_root) {
        float4 b0 = *(const float4*)(bias + iter * HH + og * 8);
        float4 b1 = *(const float4*)(bias + iter * HH + og * 8 + 4);
#pragma unroll
        for (int a = 0; a < 8; a++) {
            acc[a][0] = b0.x; acc[a][1] = b0.y; acc[a][2] = b0.z; acc[a][3] = b0.w;
            acc[a][4] = b1.x; acc[a][5] = b1.y; acc[a][6] = b1.z; acc[a][7] = b1.w;
        }
    } else {
#pragma unroll
        for (int a = 0; a < 8; a++)
#pragma unroll
            for (int b = 0; b < 8; b++) acc[a][b] = 0.f;
    }

#pragma unroll 4
    for (int k = 0; k < HH; k++) {
        float4 h0 = *(const float4*)&hsT[k][rg * 8];
        float4 h1 = *(const float4*)&hsT[k][rg * 8 + 4];
        float4 w0 = *(const float4*)&ws[k * HH + og * 8];
        float4 w1 = *(const float4*)&ws[k * HH + og * 8 + 4];
        float hh[8] = {h0.x, h0.y, h0.z, h0.w, h1.x, h1.y, h1.z, h1.w};
        float wv[8] = {w0.x, w0.y, w0.z, w0.w, w1.x, w1.y, w1.z, w1.w};
#pragma unroll
        for (int a = 0; a < 8; a++)
#pragma unroll
            for (int b = 0; b < 8; b++)
                acc[a][b] += hh[a] * wv[b];
    }

#pragma unroll
    for (int a = 0; a < 8; a++) {
        int d = sdst[rg * 8 + a];
        if (d >= 0) {
            float* dr = hout + d * HH + og * 8;
            red_v4(dr,     acc[a][0], acc[a][1], acc[a][2], acc[a][3]);
            red_v4(dr + 4, acc[a][4], acc[a][5], acc[a][6], acc[a][7]);
        }
    }
}

// ======== fully fused Set2Set: 4 iterations + output MLP in one kernel =====
__global__ __launch_bounds__(256) void k_s2s_all(const float* __restrict__ W_ih,
                                                 const float* __restrict__ W_hh,
                                                 const float* __restrict__ b_ih,
                                                 const float* __restrict__ b_hh,
                                                 const float* __restrict__ W_o1,
                                                 const float* __restrict__ b_o1,
                                                 const float* __restrict__ W_o2,
                                                 const float* __restrict__ b_o2,
                                                 float* __restrict__ out) {
    const float* h = g_hA;          // final node states after MPI=3 (A->B->C->A)
    int b = blockIdx.x;
    int tid = threadIdx.x;

    __shared__ float hcache[SMAX * HH];   // 40KB
    __shared__ float qs[2 * HH];
    __shared__ float gates[4 * HH];
    __shared__ float q[HH];
    __shared__ float hx_s[HH];
    __shared__ float cx_s[HH];
    __shared__ float red[256];
    __shared__ float r4[4][HH];

    int s = g_seg[b], t = g_seg[b + 1];
    int len = t - s;
    int nc = len < SMAX ? len : SMAX;

    {
        float4* d4 = (float4*)hcache;
        const float4* s4 = (const float4*)(h + s * HH);
        int tot = nc * (HH / 4);
        for (int i = tid; i < tot; i += 256) d4[i] = s4[i];
    }
    if (tid < 2 * HH) qs[tid] = 0.f;
    if (tid < HH) { hx_s[tid] = 0.f; cx_s[tid] = 0.f; }
    __syncthreads();

    for (int it = 0; it < S2S; it++) {
        {
            float g = b_ih[tid] + b_hh[tid];
            const float* wi = W_ih + tid * 2 * HH;
#pragma unroll 8
            for (int k = 0; k < 2 * HH; k++) g += qs[k] * wi[k];
            const float* wh = W_hh + tid * HH;
#pragma unroll 8
            for (int k = 0; k < HH; k++) g += hx_s[k] * wh[k];
            gates[tid] = g;
        }
        __syncthreads();
        if (tid < HH) {
            float ig = gates[tid], fg = gates[HH + tid];
            float gg = gates[2 * HH + tid], og = gates[3 * HH + tid];
            float si = 1.f / (1.f + expf(-ig));
            float sf = 1.f / (1.f + expf(-fg));
            float so = 1.f / (1.f + expf(-og));
            float c = sf * cx_s[tid] + si * tanhf(gg);
            cx_s[tid] = c;
            float hx = so * tanhf(c);
            hx_s[tid] = hx;
            q[tid] = hx;
        }
        __syncthreads();

        float lmax = -1e30f;
        const float4* q4 = (const float4*)q;
        for (int l = tid; l < len; l += 256) {
            const float4* hr = (l < nc) ? (const float4*)&hcache[l * HH]
                                        : (const float4*)(h + (s + l) * HH);
            float e = 0.f;
#pragma unroll
            for (int k = 0; k < HH / 4; k++) {
                float4 hv = hr[k];
                float4 qv = q4[k];
                e += hv.x * qv.x + hv.y * qv.y + hv.z * qv.z + hv.w * qv.w;
            }
            g_e[s + l] = e;
            lmax = fmaxf(lmax, e);
        }
        red[tid] = lmax; __syncthreads();
        for (int w = 128; w > 0; w >>= 1) {
            if (tid < w) red[tid] = fmaxf(red[tid], red[tid + w]);
            __syncthreads();
        }
        float m = red[0];
        __syncthreads();

        float lsum = 0.f;
        for (int l = tid; l < len; l += 256) {
            float a = expf(g_e[s + l] - m);
            g_a[s + l] = a;
            lsum += a;
        }
        red[tid] = lsum; __syncthreads();
        for (int w = 128; w > 0; w >>= 1) {
            if (tid < w) red[tid] += red[tid + w];
            __syncthreads();
        }
        float denom = red[0];
        if (denom == 0.f) denom = 1.f;
        __syncthreads();

        {
            int part = tid >> 6;
            int o = tid & 63;
            float r = 0.f;
            for (int l = part; l < len; l += 4) {
                float hv = (l < nc) ? hcache[l * HH + o] : h[(s + l) * HH + o];
                r += g_a[s + l] * hv;
            }
            r4[part][o] = r;
        }
        __syncthreads();
        if (tid < HH) {
            float r = (r4[0][tid] + r4[1][tid] + r4[2][tid] + r4[3][tid]) / denom;
            qs[tid]      = q[tid];
            qs[HH + tid] = r;
        }
        __syncthreads();
    }

    if (tid < HH) {
        float v = b_o1[tid];
#pragma unroll 8
        for (int k = 0; k < 2 * HH; k++) v += qs[k] * W_o1[k * HH + tid];
        v = fmaxf(v, 0.f);
        red[tid] = v * W_o2[tid];
    }
    __syncthreads();
    for (int w = 32; w > 0; w >>= 1) {
        if (tid < w) red[tid] += red[tid + w];
        __syncthreads();
    }
    if (tid == 0) out[b] = red[0] + b_o2[0];
}

// ---------------------------------------------------------------------------
extern "C" void kernel_launch(void* const* d_in, const int* in_sizes, int n_in,
                              void* d_out, int out_size) {
    const float* node_feat = (const float*)d_in[0];
    const int*   node_type = (const int*)d_in[1];
    const int*   edge_index= (const int*)d_in[2];
    const int*   etype     = (const int*)d_in[3];
    const int*   batch     = (const int*)d_in[4];
    const float* W_emb     = (const float*)d_in[5];
    const float* b_emb     = (const float*)d_in[6];
    const float* W_e1      = (const float*)d_in[7];
    const float* b_e1      = (const float*)d_in[8];
    const float* W_e2      = (const float*)d_in[9];
    const float* b_e2      = (const float*)d_in[10];
    const float* roots     = (const float*)d_in[11];
    const float* conv_bias = (const float*)d_in[12];
    const float* W_ih      = (const float*)d_in[13];
    const float* W_hh      = (const float*)d_in[14];
    const float* b_ih      = (const float*)d_in[15];
    const float* b_hh      = (const float*)d_in[16];
    const float* W_o1      = (const float*)d_in[17];
    const float* b_o1      = (const float*)d_in[18];
    const float* W_o2      = (const float*)d_in[19];
    const float* b_o2      = (const float*)d_in[20];
    float* out = (float*)d_out;

    const int* src = edge_index;
    const int* dst = edge_index + EE;

    k_setup<<<(EE + 255) / 256, 256>>>(batch, etype);
    k_front<<<SCB + 64 + NN / 4, 256>>>(etype, src, dst,
                                        W_e1, b_e1, W_e2, b_e2,
                                        node_feat, node_type, W_emb, b_emb);

    // 3-buffer rotation: (in, out, zero)
    k_mp<<<GRIDMP, 128>>>(0, 1, 2, 0, roots, conv_bias);  // A->B, zero C
    k_mp<<<GRIDMP, 128>>>(1, 2, 0, 1, roots, conv_bias);  // B->C, zero A
    k_mp<<<GRIDMP, 128>>>(2, 0, -1, 2, roots, conv_bias); // C->A

    k_s2s_all<<<BB, 256>>>(W_ih, W_hh, b_ih, b_hh,
                           W_o1, b_o1, W_o2, b_o2, out);
}

// round 11
// speedup vs baseline: 1.9931x; 1.4787x over previous
#include <cuda_runtime.h>

#define NN 20000
#define EE 50000
#define BB 128
#define HH 64
#define FEATD 28
#define NTYPES 100
#define EDIM 5
#define MPI 3
#define S2S 4

#define TE 128                       // edges/nodes per GEMM tile
#define EDGETILES (EE / TE + EDIM)   // worst-case edge tile count = 395
#define ROOTTILES ((NN + TE - 1) / TE)  // 157
#define GRIDMP (ROOTTILES + EDGETILES)
#define ZTOT (NN * HH / 4)           // float4 count of one h buffer
#define SMAX 160                     // cached h rows per graph in k_s2s_all
#define SA 512                       // smem softmax-weight slots per graph
#define SCB ((EE + 255) / 256)       // scatter blocks in fused front kernel

// ---------------- scratch (device globals; no allocation allowed) ----------
__device__ float g_hA[NN * HH];
__device__ float g_hB[NN * HH];
__device__ float g_hC[NN * HH];
__device__ float g_Wmat[EDIM * HH * HH];
__device__ float g_WihT[2 * HH * 4 * HH];   // [128][256] transposed W_ih
__device__ float g_WhhT[HH * 4 * HH];       // [64][256]  transposed W_hh
__device__ float g_a[NN];                   // softmax spill (len > SA only)
__device__ int   g_seg[BB + 1];
__device__ int   g_tcnt[EDIM];
__device__ int   g_tptr[EDIM];
__device__ int   g_toff[EDIM + 1];
__device__ int   g_tileoff[EDIM + 1];
__device__ int   g_psrc[EE];
__device__ int   g_pdst[EE];
__device__ int   g_done = 0;

__device__ __forceinline__ float* hsel(int id) {
    return id == 0 ? g_hA : (id == 1 ? g_hB : g_hC);
}

__device__ __forceinline__ void red_v4(float* p, float a, float b, float c, float d) {
    asm volatile("red.global.add.v4.f32 [%0], {%1, %2, %3, %4};"
                 :: "l"(p), "f"(a), "f"(b), "f"(c), "f"(d) : "memory");
}

// ======== setup: seg bounds + type hist + (last block) scan ================
__global__ void k_setup(const int* __restrict__ batch,
                        const int* __restrict__ etype) {
    __shared__ int sh[EDIM];
    int tid = threadIdx.x;
    int gid = blockIdx.x * blockDim.x + tid;

    if (tid < EDIM) sh[tid] = 0;

    if (blockIdx.x == 0 && tid <= BB) {
        if (tid == BB) g_seg[BB] = NN;
        else {
            int lo = 0, hi = NN;
            while (lo < hi) {
                int mid = (lo + hi) >> 1;
                if (batch[mid] < tid) lo = mid + 1; else hi = mid;
            }
            g_seg[tid] = lo;
        }
    }
    __syncthreads();

    if (gid < EE) atomicAdd(&sh[etype[gid]], 1);
    __syncthreads();
    if (tid < EDIM) atomicAdd(&g_tcnt[tid], sh[tid]);
    __syncthreads();

    if (tid == 0) {
        __threadfence();
        int old = atomicAdd(&g_done, 1);
        if (old == (int)gridDim.x - 1) {
            int off = 0, toff = 0;
            for (int t = 0; t < EDIM; t++) {
                int n = atomicAdd(&g_tcnt[t], 0);
                g_toff[t] = off;
                g_tileoff[t] = toff;
                g_tptr[t] = off;
                off += n;
                toff += (n + TE - 1) / TE;
                g_tcnt[t] = 0;
            }
            g_toff[EDIM] = off;
            g_tileoff[EDIM] = toff;
            g_done = 0;
        }
    }
}

// ======== fused front: scatter + wmat + weight transposes + embedding ======
// [0, SCB): scatter. [SCB, SCB+64): wmat. [SCB+64, SCB+66): W transposes.
// [SCB+66, ...): embedding (4 nodes each) + zero g_hB slice.
__global__ void k_front(const int* __restrict__ etype,
                        const int* __restrict__ src,
                        const int* __restrict__ dst,
                        const float* __restrict__ W_e1,
                        const float* __restrict__ b_e1,
                        const float* __restrict__ W_e2,
                        const float* __restrict__ b_e2,
                        const float* __restrict__ feat,
                        const int* __restrict__ ntype,
                        const float* __restrict__ W_emb,
                        const float* __restrict__ b_emb,
                        const float* __restrict__ W_ih,
                        const float* __restrict__ W_hh) {
    int tid = threadIdx.x;
    if (blockIdx.x < SCB) {
        int e = blockIdx.x * 256 + tid;
        if (e < EE) {
            int pos = atomicAdd(&g_tptr[etype[e]], 1);
            g_psrc[pos] = src[e];
            g_pdst[pos] = dst[e];
        }
    } else if (blockIdx.x < SCB + 64) {
        __shared__ float hr[EDIM][HH];
        __shared__ float part[4][EDIM][HH];
        int wb = blockIdx.x - SCB;
        if (tid < HH) {
#pragma unroll
            for (int t = 0; t < EDIM; t++)
                hr[t][tid] = fmaxf(W_e1[t * HH + tid] + b_e1[tid], 0.f);
        }
        __syncthreads();
        int jc = tid >> 6;
        int c = tid & 63;
        int idx = wb * 64 + c;
        float a0 = 0.f, a1 = 0.f, a2 = 0.f, a3 = 0.f, a4 = 0.f;
#pragma unroll
        for (int jj = 0; jj < 16; jj++) {
            int j = jc * 16 + jj;
            float w = W_e2[j * (HH * HH) + idx];
            a0 += hr[0][j] * w;
            a1 += hr[1][j] * w;
            a2 += hr[2][j] * w;
            a3 += hr[3][j] * w;
            a4 += hr[4][j] * w;
        }
        part[jc][0][c] = a0; part[jc][1][c] = a1; part[jc][2][c] = a2;
        part[jc][3][c] = a3; part[jc][4][c] = a4;
        __syncthreads();
        if (jc == 0) {
            float bb = b_e2[idx];
#pragma unroll
            for (int t = 0; t < EDIM; t++)
                g_Wmat[t * HH * HH + idx] =
                    bb + part[0][t][c] + part[1][t][c] + part[2][t][c] + part[3][t][c];
        }
    } else if (blockIdx.x < SCB + 65) {
        // transpose W_ih [256][128] -> g_WihT [128][256] (coalesced writes)
        for (int idx = tid; idx < 2 * HH * 4 * HH; idx += 256) {
            int k = idx >> 8;          // 0..127
            int j = idx & 255;         // 0..255
            g_WihT[idx] = W_ih[j * (2 * HH) + k];
        }
    } else if (blockIdx.x < SCB + 66) {
        // transpose W_hh [256][64] -> g_WhhT [64][256]
        for (int idx = tid; idx < HH * 4 * HH; idx += 256) {
            int k = idx >> 8;          // 0..63
            int j = idx & 255;         // 0..255
            g_WhhT[idx] = W_hh[j * HH + k];
        }
    } else {
        __shared__ float sf[4][FEATD];
        int blk = blockIdx.x - SCB - 66;      // 0..4999
        int l = tid >> 6;
        int o = tid & 63;
        int node = blk * 4 + l;
        // zero g_hB for the first MP iteration's atomic accumulation
        g_hB[blk * 256 + tid] = 0.f;
        if (o < FEATD) sf[l][o] = feat[node * FEATD + o];
        __syncthreads();
        int t = ntype[node];
        float acc = b_emb[o] + W_emb[t * HH + o];
#pragma unroll
        for (int f = 0; f < FEATD; f++)
            acc += sf[l][f] * W_emb[(NTYPES + f) * HH + o];
        g_hA[node * HH + o] = acc;
    }
}

// ======== fused MP iteration: root + edge GEMM tiles, 8x8 register tiles ===
__global__ __launch_bounds__(128) void k_mp(int in_id, int out_id, int zero_id,
                                            int iter,
                                            const float* __restrict__ roots,
                                            const float* __restrict__ bias) {
    const float* hin = hsel(in_id);
    float* hout      = hsel(out_id);
    int tid = threadIdx.x;

    if (zero_id >= 0) {
        float4* z = (float4*)hsel(zero_id);
        const int chunk = (ZTOT + GRIDMP - 1) / GRIDMP;
        int lo = blockIdx.x * chunk;
        int hiz = lo + chunk; if (hiz > ZTOT) hiz = ZTOT;
        for (int i = lo + tid; i < hiz; i += 128)
            z[i] = make_float4(0.f, 0.f, 0.f, 0.f);
    }

    __shared__ float hsT[HH][TE + 8];   // [k][row]
    __shared__ float ws[HH * HH];       // [k*64+o]
    __shared__ int   sdst[TE];

    bool is_root = blockIdx.x < (unsigned)ROOTTILES;
    const float* W;
    int base;

    if (is_root) {
        base = blockIdx.x * TE;
        W = roots + iter * HH * HH;
        if (tid < TE) {
            int node = base + tid;
            sdst[tid] = (node < NN) ? node : -1;
        }
    } else {
        int tb = blockIdx.x - ROOTTILES;
        if (tb >= g_tileoff[EDIM]) return;
        int t = 0;
        while (tb >= g_tileoff[t + 1]) t++;
        base = g_toff[t] + (tb - g_tileoff[t]) * TE;
        int hi = g_toff[t + 1];
        W = g_Wmat + t * HH * HH;
        if (tid < TE) {
            int p = base + tid;
            sdst[tid] = (p < hi) ? g_pdst[p] : -1;
        }
    }

    for (int i = tid; i < HH * HH; i += 128)
        ws[i] = W[i];

    {
        int s;
        if (is_root) {
            int node = base + tid;
            s = (node < NN) ? node : 0;
        } else {
            int p = base + tid;
            s = (sdst[tid] >= 0) ? g_psrc[p] : 0;
        }
        const float4* hr = (const float4*)(hin + s * HH);
#pragma unroll
        for (int j = 0; j < 16; j++) {
            float4 v = hr[j];
            int k = j * 4;
            hsT[k + 0][tid] = v.x;
            hsT[k + 1][tid] = v.y;
            hsT[k + 2][tid] = v.z;
            hsT[k + 3][tid] = v.w;
        }
    }
    __syncthreads();

    int rg = tid >> 3;   // 0..15 row group (8 rows)
    int og = tid & 7;    // 0..7  out group (8 outs)

    float acc[8][8];
    if (is_root) {
        float4 b0 = *(const float4*)(bias + iter * HH + og * 8);
        float4 b1 = *(const float4*)(bias + iter * HH + og * 8 + 4);
#pragma unroll
        for (int a = 0; a < 8; a++) {
            acc[a][0] = b0.x; acc[a][1] = b0.y; acc[a][2] = b0.z; acc[a][3] = b0.w;
            acc[a][4] = b1.x; acc[a][5] = b1.y; acc[a][6] = b1.z; acc[a][7] = b1.w;
        }
    } else {
#pragma unroll
        for (int a = 0; a < 8; a++)
#pragma unroll
            for (int b = 0; b < 8; b++) acc[a][b] = 0.f;
    }

#pragma unroll 4
    for (int k = 0; k < HH; k++) {
        float4 h0 = *(const float4*)&hsT[k][rg * 8];
        float4 h1 = *(const float4*)&hsT[k][rg * 8 + 4];
        float4 w0 = *(const float4*)&ws[k * HH + og * 8];
        float4 w1 = *(const float4*)&ws[k * HH + og * 8 + 4];
        float hh[8] = {h0.x, h0.y, h0.z, h0.w, h1.x, h1.y, h1.z, h1.w};
        float wv[8] = {w0.x, w0.y, w0.z, w0.w, w1.x, w1.y, w1.z, w1.w};
#pragma unroll
        for (int a = 0; a < 8; a++)
#pragma unroll
            for (int b = 0; b < 8; b++)
                acc[a][b] += hh[a] * wv[b];
    }

#pragma unroll
    for (int a = 0; a < 8; a++) {
        int d = sdst[rg * 8 + a];
        if (d >= 0) {
            float* dr = hout + d * HH + og * 8;
            red_v4(dr,     acc[a][0], acc[a][1], acc[a][2], acc[a][3]);
            red_v4(dr + 4, acc[a][4], acc[a][5], acc[a][6], acc[a][7]);
        }
    }
}

// ======== fully fused Set2Set: 4 iterations + output MLP ===================
// One block per graph. e kept in registers, a in smem (spill to g_a if the
// segment exceeds SA rows). LSTM weights read via transposed coalesced arrays.
__global__ __launch_bounds__(256) void k_s2s_all(const float* __restrict__ b_ih,
                                                 const float* __restrict__ b_hh,
                                                 const float* __restrict__ W_o1,
                                                 const float* __restrict__ b_o1,
                                                 const float* __restrict__ W_o2,
                                                 const float* __restrict__ b_o2,
                                                 float* __restrict__ out) {
    const float* h = g_hA;          // final node states after MPI=3 (A->B->C->A)
    int b = blockIdx.x;
    int tid = threadIdx.x;

    __shared__ float hcache[SMAX * HH];   // 40KB
    __shared__ float sa[SA];              // softmax weights
    __shared__ float qs[2 * HH];
    __shared__ float gates[4 * HH];
    __shared__ float q[HH];
    __shared__ float hx_s[HH];
    __shared__ float cx_s[HH];
    __shared__ float red[256];
    __shared__ float r4[4][HH];

    int s = g_seg[b], t = g_seg[b + 1];
    int len = t - s;
    int nc = len < SMAX ? len : SMAX;

    {
        float4* d4 = (float4*)hcache;
        const float4* s4 = (const float4*)(h + s * HH);
        int tot = nc * (HH / 4);
        for (int i = tid; i < tot; i += 256) d4[i] = s4[i];
    }
    if (tid < 2 * HH) qs[tid] = 0.f;
    if (tid < HH) { hx_s[tid] = 0.f; cx_s[tid] = 0.f; }
    __syncthreads();

    float ev[8];   // per-thread scores (supports len <= 2048)

    for (int it = 0; it < S2S; it++) {
        // ---- LSTM gates (coalesced transposed weights, 2 accumulators) ----
        {
            float g0 = b_ih[tid];
            float g1 = b_hh[tid];
#pragma unroll 8
            for (int k = 0; k < 2 * HH; k++) g0 += qs[k] * g_WihT[k * 256 + tid];
#pragma unroll 8
            for (int k = 0; k < HH; k++)     g1 += hx_s[k] * g_WhhT[k * 256 + tid];
            gates[tid] = g0 + g1;
        }
        __syncthreads();
        if (tid < HH) {
            float ig = gates[tid], fg = gates[HH + tid];
            float gg = gates[2 * HH + tid], og = gates[3 * HH + tid];
            float si = 1.f / (1.f + expf(-ig));
            float sf = 1.f / (1.f + expf(-fg));
            float so = 1.f / (1.f + expf(-og));
            float c = sf * cx_s[tid] + si * tanhf(gg);
            cx_s[tid] = c;
            float hx = so * tanhf(c);
            hx_s[tid] = hx;
            q[tid] = hx;
        }
        __syncthreads();

        // ---- pass 1: e = <h, q>, max (e stays in registers) ----
        float lmax = -1e30f;
        const float4* q4 = (const float4*)q;
        {
            int i = 0;
            for (int l = tid; l < len && i < 8; l += 256, i++) {
                const float4* hr = (l < nc) ? (const float4*)&hcache[l * HH]
                                            : (const float4*)(h + (s + l) * HH);
                float e = 0.f;
#pragma unroll
                for (int k = 0; k < HH / 4; k++) {
                    float4 hv = hr[k];
                    float4 qv = q4[k];
                    e += hv.x * qv.x + hv.y * qv.y + hv.z * qv.z + hv.w * qv.w;
                }
                ev[i] = e;
                lmax = fmaxf(lmax, e);
            }
        }
        red[tid] = lmax; __syncthreads();
        for (int w = 128; w > 0; w >>= 1) {
            if (tid < w) red[tid] = fmaxf(red[tid], red[tid + w]);
            __syncthreads();
        }
        float m = red[0];
        __syncthreads();

        // ---- pass 2: a = exp(e - m) into smem (spill if l >= SA) ----
        float lsum = 0.f;
        {
            int i = 0;
            for (int l = tid; l < len && i < 8; l += 256, i++) {
                float a = expf(ev[i] - m);
                if (l < SA) sa[l] = a; else g_a[s + l] = a;
                lsum += a;
            }
        }
        red[tid] = lsum; __syncthreads();
        for (int w = 128; w > 0; w >>= 1) {
            if (tid < w) red[tid] += red[tid + w];
            __syncthreads();
        }
        float denom = red[0];
        if (denom == 0.f) denom = 1.f;
        __syncthreads();

        // ---- pass 3: r[o] = sum a*h / denom, 4-way n split ----
        {
            int part = tid >> 6;
            int o = tid & 63;
            float r = 0.f;
            for (int l = part; l < len; l += 4) {
                float av = (l < SA) ? sa[l] : g_a[s + l];
                float hv = (l < nc) ? hcache[l * HH + o] : h[(s + l) * HH + o];
                r += av * hv;
            }
            r4[part][o] = r;
        }
        __syncthreads();
        if (tid < HH) {
            float r = (r4[0][tid] + r4[1][tid] + r4[2][tid] + r4[3][tid]) / denom;
            qs[tid]      = q[tid];
            qs[HH + tid] = r;
        }
        __syncthreads();
    }

    // ---- output MLP ----
    if (tid < HH) {
        float v = b_o1[tid];
#pragma unroll 8
        for (int k = 0; k < 2 * HH; k++) v += qs[k] * W_o1[k * HH + tid];
        v = fmaxf(v, 0.f);
        red[tid] = v * W_o2[tid];
    }
    __syncthreads();
    for (int w = 32; w > 0; w >>= 1) {
        if (tid < w) red[tid] += red[tid + w];
        __syncthreads();
    }
    if (tid == 0) out[b] = red[0] + b_o2[0];
}

// ---------------------------------------------------------------------------
extern "C" void kernel_launch(void* const* d_in, const int* in_sizes, int n_in,
                              void* d_out, int out_size) {
    const float* node_feat = (const float*)d_in[0];
    const int*   node_type = (const int*)d_in[1];
    const int*   edge_index= (const int*)d_in[2];
    const int*   etype     = (const int*)d_in[3];
    const int*   batch     = (const int*)d_in[4];
    const float* W_emb     = (const float*)d_in[5];
    const float* b_emb     = (const float*)d_in[6];
    const float* W_e1      = (const float*)d_in[7];
    const float* b_e1      = (const float*)d_in[8];
    const float* W_e2      = (const float*)d_in[9];
    const float* b_e2      = (const float*)d_in[10];
    const float* roots     = (const float*)d_in[11];
    const float* conv_bias = (const float*)d_in[12];
    const float* W_ih      = (const float*)d_in[13];
    const float* W_hh      = (const float*)d_in[14];
    const float* b_ih      = (const float*)d_in[15];
    const float* b_hh      = (const float*)d_in[16];
    const float* W_o1      = (const float*)d_in[17];
    const float* b_o1      = (const float*)d_in[18];
    const float* W_o2      = (const float*)d_in[19];
    const float* b_o2      = (const float*)d_in[20];
    float* out = (float*)d_out;

    const int* src = edge_index;
    const int* dst = edge_index + EE;

    k_setup<<<(EE + 255) / 256, 256>>>(batch, etype);
    k_front<<<SCB + 66 + NN / 4, 256>>>(etype, src, dst,
                                        W_e1, b_e1, W_e2, b_e2,
                                        node_feat, node_type, W_emb, b_emb,
                                        W_ih, W_hh);

    // 3-buffer rotation: (in, out, zero)
    k_mp<<<GRIDMP, 128>>>(0, 1, 2, 0, roots, conv_bias);  // A->B, zero C
    k_mp<<<GRIDMP, 128>>>(1, 2, 0, 1, roots, conv_bias);  // B->C, zero A
    k_mp<<<GRIDMP, 128>>>(2, 0, -1, 2, roots, conv_bias); // C->A

    k_s2s_all<<<BB, 256>>>(b_ih, b_hh, W_o1, b_o1, W_o2, b_o2, out);
}